// round 5
// baseline (speedup 1.0000x reference)
#include <cuda_runtime.h>
#include <cuda_bf16.h>
#include <math.h>
#include <stdint.h>

#define BB   4
#define NN   16384
#define CIN0 64
#define COUT 128
#define RR   32
#define NVOX (BB*RR*RR*RR)   /* 131072 */

typedef unsigned int u32;
typedef unsigned long long u64;

// ---------------- scratch (device globals) ------------------------------------
__device__ float g_grid[(size_t)NVOX * CIN0];
__device__ float g_cnt [NVOX];
__device__ __align__(16) __nv_bfloat16 g_g0h[(size_t)NVOX * CIN0];
__device__ __align__(16) __nv_bfloat16 g_g0l[(size_t)NVOX * CIN0];
__device__ __align__(16) __nv_bfloat16 g_h1h[(size_t)NVOX * COUT];
__device__ __align__(16) __nv_bfloat16 g_h1l[(size_t)NVOX * COUT];
__device__ float g_h2  [(size_t)NVOX * COUT];
__device__ float g_pf  [(size_t)BB * NN * COUT];
__device__ float g_stats[BB * 8 * 2];
__device__ __align__(16) __nv_bfloat16 g_w1h[27 * COUT * CIN0];   // [tap][co][ci]
__device__ __align__(16) __nv_bfloat16 g_w1l[27 * COUT * CIN0];
__device__ __align__(16) __nv_bfloat16 g_w2h[27 * COUT * COUT];
__device__ __align__(16) __nv_bfloat16 g_w2l[27 * COUT * COUT];

// ---------------- helpers -------------------------------------------------------
__device__ __forceinline__ u32 smem_u32(const void* p) {
    u32 a;
    asm("{ .reg .u64 t; cvta.to.shared.u64 t, %1; cvt.u32.u64 %0, t; }" : "=r"(a) : "l"(p));
    return a;
}
__device__ __forceinline__ void cp16(u32 dst, const void* src, u32 sz) {
    asm volatile("cp.async.cg.shared.global [%0], [%1], 16, %2;"
                 :: "r"(dst), "l"(src), "r"(sz) : "memory");
}
__device__ __forceinline__ void ldsm4(u32& r0, u32& r1, u32& r2, u32& r3, u32 a) {
    asm volatile("ldmatrix.sync.aligned.m8n8.x4.shared.b16 {%0,%1,%2,%3}, [%4];"
                 : "=r"(r0), "=r"(r1), "=r"(r2), "=r"(r3) : "r"(a));
}
__device__ __forceinline__ void mma16816(float& d0, float& d1, float& d2, float& d3,
                                         u32 a0, u32 a1, u32 a2, u32 a3,
                                         u32 b0, u32 b1) {
    asm volatile("mma.sync.aligned.m16n8k16.row.col.f32.bf16.bf16.f32 "
                 "{%0,%1,%2,%3}, {%4,%5,%6,%7}, {%8,%9}, {%0,%1,%2,%3};"
                 : "+f"(d0), "+f"(d1), "+f"(d2), "+f"(d3)
                 : "r"(a0), "r"(a1), "r"(a2), "r"(a3), "r"(b0), "r"(b1));
}

// ---------------- zero scratch --------------------------------------------------
__global__ void zero_scratch_kernel() {
    const long NG = (long)NVOX * CIN0, NC = NVOX, NS = BB * 8 * 2;
    const long total = NG + NC + NS;
    for (long i = (long)blockIdx.x * blockDim.x + threadIdx.x; i < total;
         i += (long)gridDim.x * blockDim.x) {
        if (i < NG)            g_grid[i] = 0.f;
        else if (i < NG + NC)  g_cnt[i - NG] = 0.f;
        else                   g_stats[i - NG - NC] = 0.f;
    }
}

// ---- weight prep: w[co][ci][tap] -> [tap][co][ci] bf16 hi/lo --------------------
template <int CIN>
__global__ void wprep_kernel(const float* __restrict__ w) {
    __nv_bfloat16* oh = (CIN == CIN0) ? g_w1h : g_w2h;
    __nv_bfloat16* ol = (CIN == CIN0) ? g_w1l : g_w2l;
    int total = COUT * CIN * 27;
    for (int i = blockIdx.x * blockDim.x + threadIdx.x; i < total;
         i += gridDim.x * blockDim.x) {
        int co  = i / (CIN * 27);
        int r   = i - co * (CIN * 27);
        int ci  = r / 27;
        int tap = r - ci * 27;
        float v = w[i];
        __nv_bfloat16 h = __float2bfloat16(v);
        __nv_bfloat16 l = __float2bfloat16(v - __bfloat162float(h));
        int dst = (tap * COUT + co) * CIN + ci;
        oh[dst] = h; ol[dst] = l;
    }
}

// ---------------- voxelize -------------------------------------------------------
__global__ void scatter_kernel(const float* __restrict__ coords,
                               const float* __restrict__ feats) {
    int idx = blockIdx.x * blockDim.x + threadIdx.x;
    if (idx >= BB * NN * CIN0) return;
    int ci = idx & (CIN0 - 1);
    int gp = idx >> 6;
    int b  = gp >> 14;
    int n  = gp & (NN - 1);
    float cx = coords[gp * 3 + 0] * (float)RR;
    float cy = coords[gp * 3 + 1] * (float)RR;
    float cz = coords[gp * 3 + 2] * (float)RR;
    int ix = min(max((int)floorf(cx), 0), RR - 1);
    int iy = min(max((int)floorf(cy), 0), RR - 1);
    int iz = min(max((int)floorf(cz), 0), RR - 1);
    int vox = ((b * RR + ix) * RR + iy) * RR + iz;
    atomicAdd(&g_grid[(size_t)vox * CIN0 + ci],
              feats[((size_t)b * CIN0 + ci) * NN + n]);
    if (ci == 0) atomicAdd(&g_cnt[vox], 1.0f);
}

__global__ void vox_split_kernel() {
    long total = (long)NVOX * CIN0;
    for (long i = (long)blockIdx.x * blockDim.x + threadIdx.x; i < total;
         i += (long)gridDim.x * blockDim.x) {
        long v = i >> 6;
        float c = g_cnt[v];
        float val = g_grid[i] * (1.0f / fmaxf(c, 1.0f));
        __nv_bfloat16 h = __float2bfloat16(val);
        g_g0h[i] = h;
        g_g0l[i] = __float2bfloat16(val - __bfloat162float(h));
    }
}

// ---------------- mma.sync conv: implicit GEMM + GN + SiLU ----------------------
// CTA: (b,x) slab, 4 y-rows x 32 z = M128 voxel rows; N=128 couts.
// K-chunk = 32 (2 k16 steps). Buffers: {Ah, Al, Wh, Wl} each 128 rows x 64B
// @ pitch 80B (20-bank stride: ldmatrix conflict-free), double-buffered.
// smem 80KB -> 2 CTAs/SM -> 4 warps/SMSP for latency hiding.
#define PITCH   80
#define TEN_SZ  (128 * PITCH)        /* 10240 */
#define BUF_SZ  (4 * TEN_SZ)         /* 40960 */
#define CVSMEM  (2 * BUF_SZ)         /* 81920 */

template <int CIN>
__device__ __forceinline__ void load_chunk(
    int c, int buf, u32 sb, int tid, int b, int x, int y0,
    const __nv_bfloat16* inh, const __nv_bfloat16* inl,
    const __nv_bfloat16* wph, const __nv_bfloat16* wpl) {
    constexpr int KS = CIN / 32;            // sub-chunks per tap
    const int tap = c / KS;
    const int ci0 = (c % KS) * 32;
    const int dx = tap / 9, dy = (tap / 3) % 3, dz = tap % 3;
    const int gx = x + dx - 1;
    const u32 base = sb + buf * BUF_SZ;
#pragma unroll
    for (int i = 0; i < 8; i++) {
        int unit = tid + i * 256;            // 2048 units of 16B
        int tensor = unit >> 9;              // 512 units per tensor
        int rest = unit & 511;
        int row = rest >> 2, c16 = rest & 3; // 4 x 16B per 64B row
        u32 dst = base + tensor * TEN_SZ + row * PITCH + c16 * 16;
        if (tensor < 2) {
            int gy = y0 + (row >> 5) + dy - 1;
            int gz = (row & 31) + dz - 1;
            bool ok = ((unsigned)gx < 32u) & ((unsigned)gy < 32u) & ((unsigned)gz < 32u);
            size_t off = 0;
            if (ok)
                off = ((((size_t)(b * 32 + gx)) * 32 + gy) * 32 + gz) * CIN + ci0 + c16 * 8;
            const __nv_bfloat16* src = (tensor ? inl : inh) + off;
            cp16(dst, src, ok ? 16u : 0u);
        } else {
            size_t off = ((size_t)tap * COUT + row) * CIN + ci0 + c16 * 8;
            const __nv_bfloat16* src = ((tensor == 2) ? wph : wpl) + off;
            cp16(dst, src, 16u);
        }
    }
    asm volatile("cp.async.commit_group;" ::: "memory");
}

template <int CIN>
__global__ void __launch_bounds__(256, 2)
conv_mma_kernel(const float* __restrict__ bias,
                const float* __restrict__ gamma,
                const float* __restrict__ beta) {
    extern __shared__ __align__(128) char smem[];
    constexpr int L = 27 * (CIN / 32);
    const u32 sb = smem_u32(smem);
    const int tid = threadIdx.x, w = tid >> 5, lane = tid & 31;
    const int x = blockIdx.x, y0 = blockIdx.y * 4, b = blockIdx.z;

    const __nv_bfloat16* inh = (CIN == 64) ? g_g0h : g_h1h;
    const __nv_bfloat16* inl = (CIN == 64) ? g_g0l : g_h1l;
    const __nv_bfloat16* wph = (CIN == 64) ? g_w1h : g_w2h;
    const __nv_bfloat16* wpl = (CIN == 64) ? g_w1l : g_w2l;

    float acc[16][4];
#pragma unroll
    for (int n = 0; n < 16; n++)
#pragma unroll
        for (int j = 0; j < 4; j++) acc[n][j] = 0.f;

    load_chunk<CIN>(0, 0, sb, tid, b, x, y0, inh, inl, wph, wpl);

#pragma unroll 1
    for (int c = 0; c < L; c++) {
        asm volatile("cp.async.wait_group 0;" ::: "memory");
        __syncthreads();
        if (c + 1 < L)
            load_chunk<CIN>(c + 1, (c + 1) & 1, sb, tid, b, x, y0, inh, inl, wph, wpl);

        const u32 abase = sb + (c & 1) * BUF_SZ;
        const u32 a_addr0 = abase + (w * 16 + (lane & 15)) * PITCH + (lane >> 4) * 16;
        const u32 b_row = (lane & 7) + ((lane >> 3) & 1) * 8;
        const u32 b_addr0 = abase + 2 * TEN_SZ + b_row * PITCH + (lane >> 4) * 16;
#pragma unroll
        for (int ks = 0; ks < 2; ks++) {
            u32 ah0, ah1, ah2, ah3, al0, al1, al2, al3;
            ldsm4(ah0, ah1, ah2, ah3, a_addr0 + ks * 32);
            ldsm4(al0, al1, al2, al3, a_addr0 + TEN_SZ + ks * 32);
#pragma unroll
            for (int ng = 0; ng < 8; ng++) {
                u32 wh0, wh1, wh2, wh3, wl0, wl1, wl2, wl3;
                u32 ba = b_addr0 + ng * 16 * PITCH + ks * 32;
                ldsm4(wh0, wh1, wh2, wh3, ba);
                ldsm4(wl0, wl1, wl2, wl3, ba + TEN_SZ);
                float* d0 = acc[2 * ng];
                float* d1 = acc[2 * ng + 1];
                mma16816(d0[0], d0[1], d0[2], d0[3], ah0, ah1, ah2, ah3, wh0, wh2);
                mma16816(d0[0], d0[1], d0[2], d0[3], al0, al1, al2, al3, wh0, wh2);
                mma16816(d0[0], d0[1], d0[2], d0[3], ah0, ah1, ah2, ah3, wl0, wl2);
                mma16816(d1[0], d1[1], d1[2], d1[3], ah0, ah1, ah2, ah3, wh1, wh3);
                mma16816(d1[0], d1[1], d1[2], d1[3], al0, al1, al2, al3, wh1, wh3);
                mma16816(d1[0], d1[1], d1[2], d1[3], ah0, ah1, ah2, ah3, wl1, wl3);
            }
        }
        __syncthreads();
    }

    // ---- epilogue: bias + per-voxel GN(16 ch) + SiLU, straight from fragments ----
    const int r0 = lane >> 2, cq = lane & 3;
#pragma unroll
    for (int h = 0; h < 2; h++) {
        int row_m = w * 16 + r0 + h * 8;
        int yl = row_m >> 5, z = row_m & 31;
        size_t vox = (((size_t)(b * 32 + x)) * 32 + (y0 + yl)) * 32 + z;
#pragma unroll
        for (int g = 0; g < 8; g++) {
            float v[4];
            int cA = g * 16 + cq * 2;
            int cB = g * 16 + 8 + cq * 2;
            v[0] = acc[2 * g][2 * h + 0]     + bias[cA + 0];
            v[1] = acc[2 * g][2 * h + 1]     + bias[cA + 1];
            v[2] = acc[2 * g + 1][2 * h + 0] + bias[cB + 0];
            v[3] = acc[2 * g + 1][2 * h + 1] + bias[cB + 1];
            float s = v[0] + v[1] + v[2] + v[3];
            float q = v[0] * v[0] + v[1] * v[1] + v[2] * v[2] + v[3] * v[3];
            s += __shfl_xor_sync(0xffffffffu, s, 1);
            s += __shfl_xor_sync(0xffffffffu, s, 2);
            q += __shfl_xor_sync(0xffffffffu, q, 1);
            q += __shfl_xor_sync(0xffffffffu, q, 2);
            float mu  = s * (1.0f / 16.0f);
            float var = q * (1.0f / 16.0f) - mu * mu;
            float rs  = rsqrtf(var + 1e-5f);
            float y2[4];
#pragma unroll
            for (int j = 0; j < 4; j++) {
                int col = (j < 2) ? (cA + j) : (cB + (j - 2));
                float y = (v[j] - mu) * rs * gamma[col] + beta[col];
                y2[j] = y / (1.0f + expf(-y));
            }
            if (CIN == 64) {
                __nv_bfloat16 h0 = __float2bfloat16(y2[0]);
                __nv_bfloat16 h1 = __float2bfloat16(y2[1]);
                __nv_bfloat16 h2 = __float2bfloat16(y2[2]);
                __nv_bfloat16 h3 = __float2bfloat16(y2[3]);
                __nv_bfloat162 lA; lA.x = __float2bfloat16(y2[0] - __bfloat162float(h0));
                lA.y = __float2bfloat16(y2[1] - __bfloat162float(h1));
                __nv_bfloat162 lB; lB.x = __float2bfloat16(y2[2] - __bfloat162float(h2));
                lB.y = __float2bfloat16(y2[3] - __bfloat162float(h3));
                __nv_bfloat162 hA; hA.x = h0; hA.y = h1;
                __nv_bfloat162 hB; hB.x = h2; hB.y = h3;
                *(__nv_bfloat162*)&g_h1h[vox * COUT + cA] = hA;
                *(__nv_bfloat162*)&g_h1l[vox * COUT + cA] = lA;
                *(__nv_bfloat162*)&g_h1h[vox * COUT + cB] = hB;
                *(__nv_bfloat162*)&g_h1l[vox * COUT + cB] = lB;
            } else {
                *(float2*)&g_h2[vox * COUT + cA] = make_float2(y2[0], y2[1]);
                *(float2*)&g_h2[vox * COUT + cB] = make_float2(y2[2], y2[3]);
            }
        }
    }
}

// ---------------- point branch GEMM + global group stats ------------------------
__global__ void __launch_bounds__(128)
mlp_gstats_kernel(const float* __restrict__ feats,
                  const float* __restrict__ w,
                  const float* __restrict__ bias) {
    __shared__ float s_w[CIN0 * 129];
    __shared__ float s_f[CIN0 * 32];
    const int tid = threadIdx.x;
    const int b   = blockIdx.x >> 9;
    const int n0  = (blockIdx.x & 511) * 32;

    for (int i = tid; i < COUT * CIN0; i += 128) {
        int c = i >> 6, ci = i & 63;
        s_w[ci * 129 + c] = w[i];
    }
    for (int i = tid; i < CIN0 * 32; i += 128) {
        int ci = i >> 5, p = i & 31;
        s_f[ci * 32 + p] = feats[((size_t)b * CIN0 + ci) * NN + n0 + p];
    }
    __syncthreads();

    const int c = tid;
    float bv = bias[c];
    float lsum = 0.f, lsq = 0.f;
    for (int p = 0; p < 32; p++) {
        float a = bv;
#pragma unroll 16
        for (int ci = 0; ci < CIN0; ci++)
            a += s_w[ci * 129 + c] * s_f[ci * 32 + p];
        g_pf[((size_t)b * NN + n0 + p) * COUT + c] = a;
        lsum += a; lsq += a * a;
    }
#pragma unroll
    for (int o = 8; o >= 1; o >>= 1) {
        lsum += __shfl_xor_sync(0xffffffffu, lsum, o, 16);
        lsq  += __shfl_xor_sync(0xffffffffu, lsq,  o, 16);
    }
    if ((tid & 15) == 0) {
        int g = c >> 4;
        atomicAdd(&g_stats[(b * 8 + g) * 2 + 0], lsum);
        atomicAdd(&g_stats[(b * 8 + g) * 2 + 1], lsq);
    }
}

__global__ void stats_finalize_kernel() {
    int t = threadIdx.x;
    if (t >= BB * 8) return;
    const float inv = 1.0f / (16.0f * (float)NN);
    float s = g_stats[t * 2 + 0], s2 = g_stats[t * 2 + 1];
    float mu = s * inv;
    float var = s2 * inv - mu * mu;
    g_stats[t * 2 + 0] = mu;
    g_stats[t * 2 + 1] = rsqrtf(var + 1e-5f);
}

// ---------------- devoxelize + point GN/SiLU + add ------------------------------
__global__ void __launch_bounds__(128)
devox_out_kernel(const float* __restrict__ coords,
                 const float* __restrict__ gamma,
                 const float* __restrict__ beta,
                 float* __restrict__ out) {
    __shared__ float s_o[COUT * 17];
    const int c  = threadIdx.x;
    const int p0 = blockIdx.x * 16;
    const int b  = p0 >> 14;
    const int n0 = p0 & (NN - 1);
    const int g  = c >> 4;
    const float gm = gamma[c], bt = beta[c];
    const float mu = g_stats[(b * 8 + g) * 2 + 0];
    const float rs = g_stats[(b * 8 + g) * 2 + 1];

    for (int p = 0; p < 16; p++) {
        int gp = p0 + p;
        float cx = coords[gp * 3 + 0] * (float)RR;
        float cy = coords[gp * 3 + 1] * (float)RR;
        float cz = coords[gp * 3 + 2] * (float)RR;
        float fxl = floorf(cx), fyl = floorf(cy), fzl = floorf(cz);
        int ix = min(max((int)fxl, 0), RR - 1);
        int iy = min(max((int)fyl, 0), RR - 1);
        int iz = min(max((int)fzl, 0), RR - 1);
        int hx = min(ix + 1, RR - 1), hy = min(iy + 1, RR - 1), hz = min(iz + 1, RR - 1);
        float fx = cx - fxl, fy = cy - fyl, fz = cz - fzl;

        float v = 0.f;
#pragma unroll
        for (int dx = 0; dx < 2; dx++) {
            float wx = dx ? fx : 1.f - fx;
            int X = dx ? hx : ix;
#pragma unroll
            for (int dy = 0; dy < 2; dy++) {
                float wy = dy ? fy : 1.f - fy;
                int Y = dy ? hy : iy;
#pragma unroll
                for (int dz = 0; dz < 2; dz++) {
                    float wz = dz ? fz : 1.f - fz;
                    int Z = dz ? hz : iz;
                    size_t base = (((size_t)(b * RR + X) * RR + Y) * RR + Z) * COUT + c;
                    v += (wx * wy * wz) * g_h2[base];
                }
            }
        }
        float pv = g_pf[((size_t)gp) * COUT + c];
        float y  = (pv - mu) * rs * gm + bt;
        y = y / (1.0f + expf(-y));
        s_o[c * 17 + p] = v + y;
    }
    __syncthreads();
    for (int i = threadIdx.x; i < COUT * 16; i += 128) {
        int c2 = i >> 4, p = i & 15;
        out[((size_t)b * COUT + c2) * NN + n0 + p] = s_o[c2 * 17 + p];
    }
}

// ---------------- launch ----------------------------------------------------------
extern "C" void kernel_launch(void* const* d_in, const int* in_sizes, int n_in,
                              void* d_out, int out_size) {
    const float* coords   = (const float*)d_in[0];
    const float* features = (const float*)d_in[1];
    const float* conv1_w  = (const float*)d_in[2];
    const float* conv1_b  = (const float*)d_in[3];
    const float* gn1_g    = (const float*)d_in[4];
    const float* gn1_b    = (const float*)d_in[5];
    const float* conv2_w  = (const float*)d_in[6];
    const float* conv2_b  = (const float*)d_in[7];
    const float* gn2_g    = (const float*)d_in[8];
    const float* gn2_b    = (const float*)d_in[9];
    const float* mlp_w    = (const float*)d_in[10];
    const float* mlp_b    = (const float*)d_in[11];
    const float* gnp_g    = (const float*)d_in[12];
    const float* gnp_b    = (const float*)d_in[13];
    float* out = (float*)d_out;

    static int attr_done = 0;
    if (!attr_done) {
        cudaFuncSetAttribute(conv_mma_kernel<CIN0>,
                             cudaFuncAttributeMaxDynamicSharedMemorySize, CVSMEM);
        cudaFuncSetAttribute(conv_mma_kernel<COUT>,
                             cudaFuncAttributeMaxDynamicSharedMemorySize, CVSMEM);
        attr_done = 1;
    }

    zero_scratch_kernel<<<2048, 256>>>();
    wprep_kernel<CIN0><<<(COUT * CIN0 * 27 + 255) / 256, 256>>>(conv1_w);
    wprep_kernel<COUT><<<(COUT * COUT * 27 + 255) / 256, 256>>>(conv2_w);

    scatter_kernel<<<(BB * NN * CIN0 + 255) / 256, 256>>>(coords, features);
    vox_split_kernel<<<4096, 256>>>();

    dim3 cgrid(RR, 8, BB);   // x, y-tile, b
    conv_mma_kernel<CIN0><<<cgrid, 256, CVSMEM>>>(conv1_b, gn1_g, gn1_b);
    conv_mma_kernel<COUT><<<cgrid, 256, CVSMEM>>>(conv2_b, gn2_g, gn2_b);

    mlp_gstats_kernel<<<BB * (NN / 32), 128>>>(features, mlp_w, mlp_b);
    stats_finalize_kernel<<<1, 32>>>();

    devox_out_kernel<<<BB * NN / 16, 128>>>(coords, gnp_g, gnp_b, out);
}

// round 6
// speedup vs baseline: 1.2955x; 1.2955x over previous
#include <cuda_runtime.h>
#include <cuda_fp16.h>
#include <math.h>
#include <stdint.h>

#define BB   4
#define NN   16384
#define CIN0 64
#define COUT 128
#define RR   32
#define NVOX (BB*RR*RR*RR)   /* 131072 */

typedef unsigned int u32;
typedef unsigned long long u64;

// ---------------- scratch (device globals) ------------------------------------
__device__ float g_grid[(size_t)NVOX * CIN0];
__device__ float g_cnt [NVOX];
__device__ __align__(16) __half g_g0h[(size_t)NVOX * CIN0];   // conv1 in hi
__device__ __align__(16) __half g_g0l[(size_t)NVOX * CIN0];   // conv1 in lo
__device__ __align__(16) __half g_h1h[(size_t)NVOX * COUT];   // conv2 in hi
__device__ __align__(16) __half g_h1l[(size_t)NVOX * COUT];   // conv2 in lo
__device__ float g_h2  [(size_t)NVOX * COUT];
__device__ float g_pf  [(size_t)BB * NN * COUT];
__device__ float g_stats[BB * 8 * 2];
__device__ __align__(16) __half g_w1[27 * COUT * CIN0];       // [tap][co][ci] fp16
__device__ __align__(16) __half g_w2[27 * COUT * COUT];

// ---------------- helpers -------------------------------------------------------
__device__ __forceinline__ u32 smem_u32(const void* p) {
    u32 a;
    asm("{ .reg .u64 t; cvta.to.shared.u64 t, %1; cvt.u32.u64 %0, t; }" : "=r"(a) : "l"(p));
    return a;
}
__device__ __forceinline__ void cp16(u32 dst, const void* src, u32 sz) {
    asm volatile("cp.async.cg.shared.global [%0], [%1], 16, %2;"
                 :: "r"(dst), "l"(src), "r"(sz) : "memory");
}
__device__ __forceinline__ void ldsm4(u32& r0, u32& r1, u32& r2, u32& r3, u32 a) {
    asm volatile("ldmatrix.sync.aligned.m8n8.x4.shared.b16 {%0,%1,%2,%3}, [%4];"
                 : "=r"(r0), "=r"(r1), "=r"(r2), "=r"(r3) : "r"(a));
}
__device__ __forceinline__ void mma16816(float& d0, float& d1, float& d2, float& d3,
                                         u32 a0, u32 a1, u32 a2, u32 a3,
                                         u32 b0, u32 b1) {
    asm volatile("mma.sync.aligned.m16n8k16.row.col.f32.f16.f16.f32 "
                 "{%0,%1,%2,%3}, {%4,%5,%6,%7}, {%8,%9}, {%0,%1,%2,%3};"
                 : "+f"(d0), "+f"(d1), "+f"(d2), "+f"(d3)
                 : "r"(a0), "r"(a1), "r"(a2), "r"(a3), "r"(b0), "r"(b1));
}

// ---------------- zero scratch --------------------------------------------------
__global__ void zero_scratch_kernel() {
    const long NG = (long)NVOX * CIN0, NC = NVOX, NS = BB * 8 * 2;
    const long total = NG + NC + NS;
    for (long i = (long)blockIdx.x * blockDim.x + threadIdx.x; i < total;
         i += (long)gridDim.x * blockDim.x) {
        if (i < NG)            g_grid[i] = 0.f;
        else if (i < NG + NC)  g_cnt[i - NG] = 0.f;
        else                   g_stats[i - NG - NC] = 0.f;
    }
}

// ---- weight prep: w[co][ci][tap] -> [tap][co][ci] fp16 --------------------------
template <int CIN>
__global__ void wprep_kernel(const float* __restrict__ w) {
    __half* dst = (CIN == CIN0) ? g_w1 : g_w2;
    int total = COUT * CIN * 27;
    for (int i = blockIdx.x * blockDim.x + threadIdx.x; i < total;
         i += gridDim.x * blockDim.x) {
        int co  = i / (CIN * 27);
        int r   = i - co * (CIN * 27);
        int ci  = r / 27;
        int tap = r - ci * 27;
        dst[(tap * COUT + co) * CIN + ci] = __float2half_rn(w[i]);
    }
}

// ---------------- voxelize -------------------------------------------------------
__global__ void scatter_kernel(const float* __restrict__ coords,
                               const float* __restrict__ feats) {
    int idx = blockIdx.x * blockDim.x + threadIdx.x;
    if (idx >= BB * NN * CIN0) return;
    int ci = idx & (CIN0 - 1);
    int gp = idx >> 6;
    int b  = gp >> 14;
    int n  = gp & (NN - 1);
    float cx = coords[gp * 3 + 0] * (float)RR;
    float cy = coords[gp * 3 + 1] * (float)RR;
    float cz = coords[gp * 3 + 2] * (float)RR;
    int ix = min(max((int)floorf(cx), 0), RR - 1);
    int iy = min(max((int)floorf(cy), 0), RR - 1);
    int iz = min(max((int)floorf(cz), 0), RR - 1);
    int vox = ((b * RR + ix) * RR + iy) * RR + iz;
    atomicAdd(&g_grid[(size_t)vox * CIN0 + ci],
              feats[((size_t)b * CIN0 + ci) * NN + n]);
    if (ci == 0) atomicAdd(&g_cnt[vox], 1.0f);
}

__global__ void vox_split_kernel() {
    long total = (long)NVOX * CIN0;
    for (long i = (long)blockIdx.x * blockDim.x + threadIdx.x; i < total;
         i += (long)gridDim.x * blockDim.x) {
        long v = i >> 6;
        float c = g_cnt[v];
        float val = g_grid[i] * (1.0f / fmaxf(c, 1.0f));
        __half h = __float2half_rn(val);
        g_g0h[i] = h;
        g_g0l[i] = __float2half_rn(val - __half2float(h));
    }
}

// ---------------- mma.sync conv (fp16 2-term) + GN + SiLU -----------------------
// CTA: (b,x) slab, 4 y-rows x 32 z = M128 rows; N=128 couts; K-chunk = 64.
// Buffers: {Ah, Al, Wh} each 128 rows x 128B @ pitch 144B, double-buffered.
#define PITCH   144
#define TEN_SZ  (128 * PITCH)        /* 18432 */
#define BUF_SZ  (3 * TEN_SZ)         /* 55296 */
#define CVSMEM  (2 * BUF_SZ)         /* 110592 */

template <int CIN>
__device__ __forceinline__ void load_chunk(
    int c, int buf, u32 sb, int tid, int b, int x, int y0,
    const __half* inh, const __half* inl, const __half* wp) {
    const int tap = (CIN == 128) ? (c >> 1) : c;
    const int ci0 = (CIN == 128) ? ((c & 1) * 64) : 0;
    const int dx = tap / 9, dy = (tap / 3) % 3, dz = tap % 3;
    const int gx = x + dx - 1;
    const u32 base = sb + buf * BUF_SZ;
#pragma unroll
    for (int i = 0; i < 12; i++) {
        int unit = tid + i * 256;            // 3072 units of 16B
        int tensor = unit >> 10;             // 1024 units per tensor
        int rest = unit & 1023;
        int row = rest >> 3, c16 = rest & 7;
        u32 dst = base + tensor * TEN_SZ + row * PITCH + c16 * 16;
        if (tensor < 2) {
            int gy = y0 + (row >> 5) + dy - 1;
            int gz = (row & 31) + dz - 1;
            bool ok = ((unsigned)gx < 32u) & ((unsigned)gy < 32u) & ((unsigned)gz < 32u);
            size_t off = 0;
            if (ok)
                off = ((((size_t)(b * 32 + gx)) * 32 + gy) * 32 + gz) * CIN + ci0 + c16 * 8;
            const __half* src = (tensor ? inl : inh) + off;
            cp16(dst, src, ok ? 16u : 0u);
        } else {
            size_t off = ((size_t)tap * COUT + row) * CIN + ci0 + c16 * 8;
            cp16(dst, wp + off, 16u);
        }
    }
    asm volatile("cp.async.commit_group;" ::: "memory");
}

template <int CIN>
__global__ void __launch_bounds__(256)
conv_mma_kernel(const float* __restrict__ bias,
                const float* __restrict__ gamma,
                const float* __restrict__ beta) {
    extern __shared__ __align__(128) char smem[];
    constexpr int L = (CIN == 128) ? 54 : 27;
    const u32 sb = smem_u32(smem);
    const int tid = threadIdx.x, w = tid >> 5, lane = tid & 31;
    const int x = blockIdx.x, y0 = blockIdx.y * 4, b = blockIdx.z;

    const __half* inh = (CIN == 64) ? g_g0h : g_h1h;
    const __half* inl = (CIN == 64) ? g_g0l : g_h1l;
    const __half* wp  = (CIN == 64) ? g_w1  : g_w2;

    float acc[16][4];
#pragma unroll
    for (int n = 0; n < 16; n++)
#pragma unroll
        for (int j = 0; j < 4; j++) acc[n][j] = 0.f;

    load_chunk<CIN>(0, 0, sb, tid, b, x, y0, inh, inl, wp);

#pragma unroll 1
    for (int c = 0; c < L; c++) {
        asm volatile("cp.async.wait_group 0;" ::: "memory");
        __syncthreads();
        if (c + 1 < L)
            load_chunk<CIN>(c + 1, (c + 1) & 1, sb, tid, b, x, y0, inh, inl, wp);

        const u32 abase = sb + (c & 1) * BUF_SZ;
        const u32 a_addr0 = abase + (w * 16 + (lane & 15)) * PITCH + (lane >> 4) * 16;
        const u32 b_row = (lane & 7) + ((lane >> 3) & 1) * 8;
        const u32 b_addr0 = abase + 2 * TEN_SZ + b_row * PITCH + (lane >> 4) * 16;
#pragma unroll
        for (int ks = 0; ks < 4; ks++) {
            u32 ah0, ah1, ah2, ah3, al0, al1, al2, al3;
            ldsm4(ah0, ah1, ah2, ah3, a_addr0 + ks * 32);
            ldsm4(al0, al1, al2, al3, a_addr0 + TEN_SZ + ks * 32);
#pragma unroll
            for (int ng = 0; ng < 8; ng++) {
                u32 wh0, wh1, wh2, wh3;
                ldsm4(wh0, wh1, wh2, wh3, b_addr0 + ng * 16 * PITCH + ks * 32);
                float* d0 = acc[2 * ng];
                float* d1 = acc[2 * ng + 1];
                mma16816(d0[0], d0[1], d0[2], d0[3], ah0, ah1, ah2, ah3, wh0, wh2);
                mma16816(d0[0], d0[1], d0[2], d0[3], al0, al1, al2, al3, wh0, wh2);
                mma16816(d1[0], d1[1], d1[2], d1[3], ah0, ah1, ah2, ah3, wh1, wh3);
                mma16816(d1[0], d1[1], d1[2], d1[3], al0, al1, al2, al3, wh1, wh3);
            }
        }
        __syncthreads();
    }

    // ---- epilogue: bias + per-voxel GN(16 ch) + SiLU, straight from fragments ----
    const int r0 = lane >> 2, cq = lane & 3;
#pragma unroll
    for (int h = 0; h < 2; h++) {
        int row_m = w * 16 + r0 + h * 8;
        int yl = row_m >> 5, z = row_m & 31;
        size_t vox = (((size_t)(b * 32 + x)) * 32 + (y0 + yl)) * 32 + z;
#pragma unroll
        for (int g = 0; g < 8; g++) {
            float v[4];
            int cA = g * 16 + cq * 2;
            int cB = g * 16 + 8 + cq * 2;
            v[0] = acc[2 * g][2 * h + 0]     + bias[cA + 0];
            v[1] = acc[2 * g][2 * h + 1]     + bias[cA + 1];
            v[2] = acc[2 * g + 1][2 * h + 0] + bias[cB + 0];
            v[3] = acc[2 * g + 1][2 * h + 1] + bias[cB + 1];
            float s = v[0] + v[1] + v[2] + v[3];
            float q = v[0] * v[0] + v[1] * v[1] + v[2] * v[2] + v[3] * v[3];
            s += __shfl_xor_sync(0xffffffffu, s, 1);
            s += __shfl_xor_sync(0xffffffffu, s, 2);
            q += __shfl_xor_sync(0xffffffffu, q, 1);
            q += __shfl_xor_sync(0xffffffffu, q, 2);
            float mu  = s * (1.0f / 16.0f);
            float var = q * (1.0f / 16.0f) - mu * mu;
            float rs  = rsqrtf(var + 1e-5f);
            float y2[4];
#pragma unroll
            for (int j = 0; j < 4; j++) {
                int col = (j < 2) ? (cA + j) : (cB + (j - 2));
                float y = (v[j] - mu) * rs * gamma[col] + beta[col];
                y2[j] = y / (1.0f + expf(-y));
            }
            if (CIN == 64) {
                __half h0 = __float2half_rn(y2[0]);
                __half h1 = __float2half_rn(y2[1]);
                __half h2 = __float2half_rn(y2[2]);
                __half h3 = __float2half_rn(y2[3]);
                __half2 hA; hA.x = h0; hA.y = h1;
                __half2 hB; hB.x = h2; hB.y = h3;
                __half2 lA; lA.x = __float2half_rn(y2[0] - __half2float(h0));
                lA.y = __float2half_rn(y2[1] - __half2float(h1));
                __half2 lB; lB.x = __float2half_rn(y2[2] - __half2float(h2));
                lB.y = __float2half_rn(y2[3] - __half2float(h3));
                *(__half2*)&g_h1h[vox * COUT + cA] = hA;
                *(__half2*)&g_h1l[vox * COUT + cA] = lA;
                *(__half2*)&g_h1h[vox * COUT + cB] = hB;
                *(__half2*)&g_h1l[vox * COUT + cB] = lB;
            } else {
                *(float2*)&g_h2[vox * COUT + cA] = make_float2(y2[0], y2[1]);
                *(float2*)&g_h2[vox * COUT + cB] = make_float2(y2[2], y2[3]);
            }
        }
    }
}

// ---------------- point branch GEMM + global group stats ------------------------
__global__ void __launch_bounds__(128)
mlp_gstats_kernel(const float* __restrict__ feats,
                  const float* __restrict__ w,
                  const float* __restrict__ bias) {
    __shared__ float s_w[CIN0 * 129];
    __shared__ float s_f[CIN0 * 32];
    const int tid = threadIdx.x;
    const int b   = blockIdx.x >> 9;
    const int n0  = (blockIdx.x & 511) * 32;

    for (int i = tid; i < COUT * CIN0; i += 128) {
        int c = i >> 6, ci = i & 63;
        s_w[ci * 129 + c] = w[i];
    }
    for (int i = tid; i < CIN0 * 32; i += 128) {
        int ci = i >> 5, p = i & 31;
        s_f[ci * 32 + p] = feats[((size_t)b * CIN0 + ci) * NN + n0 + p];
    }
    __syncthreads();

    const int c = tid;
    float bv = bias[c];
    float lsum = 0.f, lsq = 0.f;
    for (int p = 0; p < 32; p++) {
        float a = bv;
#pragma unroll 16
        for (int ci = 0; ci < CIN0; ci++)
            a += s_w[ci * 129 + c] * s_f[ci * 32 + p];
        g_pf[((size_t)b * NN + n0 + p) * COUT + c] = a;
        lsum += a; lsq += a * a;
    }
#pragma unroll
    for (int o = 8; o >= 1; o >>= 1) {
        lsum += __shfl_xor_sync(0xffffffffu, lsum, o, 16);
        lsq  += __shfl_xor_sync(0xffffffffu, lsq,  o, 16);
    }
    if ((tid & 15) == 0) {
        int g = c >> 4;
        atomicAdd(&g_stats[(b * 8 + g) * 2 + 0], lsum);
        atomicAdd(&g_stats[(b * 8 + g) * 2 + 1], lsq);
    }
}

__global__ void stats_finalize_kernel() {
    int t = threadIdx.x;
    if (t >= BB * 8) return;
    const float inv = 1.0f / (16.0f * (float)NN);
    float s = g_stats[t * 2 + 0], s2 = g_stats[t * 2 + 1];
    float mu = s * inv;
    float var = s2 * inv - mu * mu;
    g_stats[t * 2 + 0] = mu;
    g_stats[t * 2 + 1] = rsqrtf(var + 1e-5f);
}

// ---------------- devoxelize + point GN/SiLU + add ------------------------------
__global__ void __launch_bounds__(128)
devox_out_kernel(const float* __restrict__ coords,
                 const float* __restrict__ gamma,
                 const float* __restrict__ beta,
                 float* __restrict__ out) {
    __shared__ float s_o[COUT * 17];
    const int c  = threadIdx.x;
    const int p0 = blockIdx.x * 16;
    const int b  = p0 >> 14;
    const int n0 = p0 & (NN - 1);
    const int g  = c >> 4;
    const float gm = gamma[c], bt = beta[c];
    const float mu = g_stats[(b * 8 + g) * 2 + 0];
    const float rs = g_stats[(b * 8 + g) * 2 + 1];

    for (int p = 0; p < 16; p++) {
        int gp = p0 + p;
        float cx = coords[gp * 3 + 0] * (float)RR;
        float cy = coords[gp * 3 + 1] * (float)RR;
        float cz = coords[gp * 3 + 2] * (float)RR;
        float fxl = floorf(cx), fyl = floorf(cy), fzl = floorf(cz);
        int ix = min(max((int)fxl, 0), RR - 1);
        int iy = min(max((int)fyl, 0), RR - 1);
        int iz = min(max((int)fzl, 0), RR - 1);
        int hx = min(ix + 1, RR - 1), hy = min(iy + 1, RR - 1), hz = min(iz + 1, RR - 1);
        float fx = cx - fxl, fy = cy - fyl, fz = cz - fzl;

        float v = 0.f;
#pragma unroll
        for (int dx = 0; dx < 2; dx++) {
            float wx = dx ? fx : 1.f - fx;
            int X = dx ? hx : ix;
#pragma unroll
            for (int dy = 0; dy < 2; dy++) {
                float wy = dy ? fy : 1.f - fy;
                int Y = dy ? hy : iy;
#pragma unroll
                for (int dz = 0; dz < 2; dz++) {
                    float wz = dz ? fz : 1.f - fz;
                    int Z = dz ? hz : iz;
                    size_t base = (((size_t)(b * RR + X) * RR + Y) * RR + Z) * COUT + c;
                    v += (wx * wy * wz) * g_h2[base];
                }
            }
        }
        float pv = g_pf[((size_t)gp) * COUT + c];
        float y  = (pv - mu) * rs * gm + bt;
        y = y / (1.0f + expf(-y));
        s_o[c * 17 + p] = v + y;
    }
    __syncthreads();
    for (int i = threadIdx.x; i < COUT * 16; i += 128) {
        int c2 = i >> 4, p = i & 15;
        out[((size_t)b * COUT + c2) * NN + n0 + p] = s_o[c2 * 17 + p];
    }
}

// ---------------- launch ----------------------------------------------------------
extern "C" void kernel_launch(void* const* d_in, const int* in_sizes, int n_in,
                              void* d_out, int out_size) {
    const float* coords   = (const float*)d_in[0];
    const float* features = (const float*)d_in[1];
    const float* conv1_w  = (const float*)d_in[2];
    const float* conv1_b  = (const float*)d_in[3];
    const float* gn1_g    = (const float*)d_in[4];
    const float* gn1_b    = (const float*)d_in[5];
    const float* conv2_w  = (const float*)d_in[6];
    const float* conv2_b  = (const float*)d_in[7];
    const float* gn2_g    = (const float*)d_in[8];
    const float* gn2_b    = (const float*)d_in[9];
    const float* mlp_w    = (const float*)d_in[10];
    const float* mlp_b    = (const float*)d_in[11];
    const float* gnp_g    = (const float*)d_in[12];
    const float* gnp_b    = (const float*)d_in[13];
    float* out = (float*)d_out;

    static int attr_done = 0;
    if (!attr_done) {
        cudaFuncSetAttribute(conv_mma_kernel<CIN0>,
                             cudaFuncAttributeMaxDynamicSharedMemorySize, CVSMEM);
        cudaFuncSetAttribute(conv_mma_kernel<COUT>,
                             cudaFuncAttributeMaxDynamicSharedMemorySize, CVSMEM);
        attr_done = 1;
    }

    zero_scratch_kernel<<<2048, 256>>>();
    wprep_kernel<CIN0><<<(COUT * CIN0 * 27 + 255) / 256, 256>>>(conv1_w);
    wprep_kernel<COUT><<<(COUT * COUT * 27 + 255) / 256, 256>>>(conv2_w);

    scatter_kernel<<<(BB * NN * CIN0 + 255) / 256, 256>>>(coords, features);
    vox_split_kernel<<<4096, 256>>>();

    dim3 cgrid(RR, 8, BB);   // x, y-tile, b
    conv_mma_kernel<CIN0><<<cgrid, 256, CVSMEM>>>(conv1_b, gn1_g, gn1_b);
    conv_mma_kernel<COUT><<<cgrid, 256, CVSMEM>>>(conv2_b, gn2_g, gn2_b);

    mlp_gstats_kernel<<<BB * (NN / 32), 128>>>(features, mlp_w, mlp_b);
    stats_finalize_kernel<<<1, 32>>>();

    devox_out_kernel<<<BB * NN / 16, 128>>>(coords, gnp_g, gnp_b, out);
}

// round 7
// speedup vs baseline: 1.8825x; 1.4531x over previous
#include <cuda_runtime.h>
#include <cuda_fp16.h>
#include <math.h>
#include <stdint.h>

#define BB   4
#define NN   16384
#define CIN0 64
#define COUT 128
#define RR   32
#define NVOX (BB*RR*RR*RR)   /* 131072 */

typedef unsigned int u32;
typedef unsigned long long u64;

// ---------------- scratch (device globals) ------------------------------------
__device__ float g_grid[(size_t)NVOX * CIN0];
__device__ float g_cnt [NVOX];
__device__ __align__(16) __half g_g0[(size_t)NVOX * CIN0];    // conv1 in (fp16)
__device__ __align__(16) __half g_h1[(size_t)NVOX * COUT];    // conv2 in (fp16)
__device__ float g_h2  [(size_t)NVOX * COUT];
__device__ float g_pf  [(size_t)BB * NN * COUT];
__device__ float g_stats[BB * 8 * 2];
__device__ __align__(16) __half g_w1[27 * COUT * CIN0];       // [tap][co][ci] fp16
__device__ __align__(16) __half g_w2[27 * COUT * COUT];

// ---------------- helpers -------------------------------------------------------
__device__ __forceinline__ u32 smem_u32(const void* p) {
    u32 a;
    asm("{ .reg .u64 t; cvta.to.shared.u64 t, %1; cvt.u32.u64 %0, t; }" : "=r"(a) : "l"(p));
    return a;
}
__device__ __forceinline__ void cp16(u32 dst, const void* src, u32 sz) {
    asm volatile("cp.async.cg.shared.global [%0], [%1], 16, %2;"
                 :: "r"(dst), "l"(src), "r"(sz) : "memory");
}
__device__ __forceinline__ void ldsm4(u32& r0, u32& r1, u32& r2, u32& r3, u32 a) {
    asm volatile("ldmatrix.sync.aligned.m8n8.x4.shared.b16 {%0,%1,%2,%3}, [%4];"
                 : "=r"(r0), "=r"(r1), "=r"(r2), "=r"(r3) : "r"(a));
}
__device__ __forceinline__ void mma16816(float& d0, float& d1, float& d2, float& d3,
                                         u32 a0, u32 a1, u32 a2, u32 a3,
                                         u32 b0, u32 b1) {
    asm volatile("mma.sync.aligned.m16n8k16.row.col.f32.f16.f16.f32 "
                 "{%0,%1,%2,%3}, {%4,%5,%6,%7}, {%8,%9}, {%0,%1,%2,%3};"
                 : "+f"(d0), "+f"(d1), "+f"(d2), "+f"(d3)
                 : "r"(a0), "r"(a1), "r"(a2), "r"(a3), "r"(b0), "r"(b1));
}

// ---------------- zero scratch --------------------------------------------------
__global__ void zero_scratch_kernel() {
    const long NG = (long)NVOX * CIN0, NC = NVOX, NS = BB * 8 * 2;
    const long total = NG + NC + NS;
    for (long i = (long)blockIdx.x * blockDim.x + threadIdx.x; i < total;
         i += (long)gridDim.x * blockDim.x) {
        if (i < NG)            g_grid[i] = 0.f;
        else if (i < NG + NC)  g_cnt[i - NG] = 0.f;
        else                   g_stats[i - NG - NC] = 0.f;
    }
}

// ---- weight prep: w[co][ci][tap] -> [tap][co][ci] fp16 --------------------------
template <int CIN>
__global__ void wprep_kernel(const float* __restrict__ w) {
    __half* dst = (CIN == CIN0) ? g_w1 : g_w2;
    int total = COUT * CIN * 27;
    for (int i = blockIdx.x * blockDim.x + threadIdx.x; i < total;
         i += gridDim.x * blockDim.x) {
        int co  = i / (CIN * 27);
        int r   = i - co * (CIN * 27);
        int ci  = r / 27;
        int tap = r - ci * 27;
        dst[(tap * COUT + co) * CIN + ci] = __float2half_rn(w[i]);
    }
}

// ---------------- voxelize -------------------------------------------------------
__global__ void scatter_kernel(const float* __restrict__ coords,
                               const float* __restrict__ feats) {
    int idx = blockIdx.x * blockDim.x + threadIdx.x;
    if (idx >= BB * NN * CIN0) return;
    int ci = idx & (CIN0 - 1);
    int gp = idx >> 6;
    int b  = gp >> 14;
    int n  = gp & (NN - 1);
    float cx = coords[gp * 3 + 0] * (float)RR;
    float cy = coords[gp * 3 + 1] * (float)RR;
    float cz = coords[gp * 3 + 2] * (float)RR;
    int ix = min(max((int)floorf(cx), 0), RR - 1);
    int iy = min(max((int)floorf(cy), 0), RR - 1);
    int iz = min(max((int)floorf(cz), 0), RR - 1);
    int vox = ((b * RR + ix) * RR + iy) * RR + iz;
    atomicAdd(&g_grid[(size_t)vox * CIN0 + ci],
              feats[((size_t)b * CIN0 + ci) * NN + n]);
    if (ci == 0) atomicAdd(&g_cnt[vox], 1.0f);
}

__global__ void vox_split_kernel() {
    long total = (long)NVOX * CIN0;
    for (long i = (long)blockIdx.x * blockDim.x + threadIdx.x; i < total;
         i += (long)gridDim.x * blockDim.x) {
        long v = i >> 6;
        float c = g_cnt[v];
        float val = g_grid[i] * (1.0f / fmaxf(c, 1.0f));
        g_g0[i] = __float2half_rn(val);
    }
}

// ---------------- mma.sync conv (fp16) + GN + SiLU ------------------------------
// CTA: (b,x) slab, 4 y-rows x 32 z = M128 rows; N=128 couts; K-chunk = 64.
// Buffers: {A, W} each 128 rows x 128B @ pitch 144B, double-buffered (72 KB).
#define PITCH   144
#define TEN_SZ  (128 * PITCH)        /* 18432 */
#define BUF_SZ  (2 * TEN_SZ)         /* 36864 */
#define CVSMEM  (2 * BUF_SZ)         /* 73728 */

template <int CIN>
__device__ __forceinline__ void load_chunk(
    int c, int buf, u32 sb, int tid, int b, int x, int y0,
    const __half* in, const __half* wp) {
    const int tap = (CIN == 128) ? (c >> 1) : c;
    const int ci0 = (CIN == 128) ? ((c & 1) * 64) : 0;
    const int dx = tap / 9, dy = (tap / 3) % 3, dz = tap % 3;
    const int gx = x + dx - 1;
    const u32 base = sb + buf * BUF_SZ;
#pragma unroll
    for (int i = 0; i < 8; i++) {
        int unit = tid + i * 256;            // 2048 units of 16B
        int tensor = unit >> 10;             // 1024 units per tensor
        int rest = unit & 1023;
        int row = rest >> 3, c16 = rest & 7;
        u32 dst = base + tensor * TEN_SZ + row * PITCH + c16 * 16;
        if (tensor == 0) {
            int gy = y0 + (row >> 5) + dy - 1;
            int gz = (row & 31) + dz - 1;
            bool ok = ((unsigned)gx < 32u) & ((unsigned)gy < 32u) & ((unsigned)gz < 32u);
            size_t off = 0;
            if (ok)
                off = ((((size_t)(b * 32 + gx)) * 32 + gy) * 32 + gz) * CIN + ci0 + c16 * 8;
            cp16(dst, in + off, ok ? 16u : 0u);
        } else {
            size_t off = ((size_t)tap * COUT + row) * CIN + ci0 + c16 * 8;
            cp16(dst, wp + off, 16u);
        }
    }
    asm volatile("cp.async.commit_group;" ::: "memory");
}

template <int CIN>
__global__ void __launch_bounds__(256)
conv_mma_kernel(const float* __restrict__ bias,
                const float* __restrict__ gamma,
                const float* __restrict__ beta) {
    extern __shared__ __align__(128) char smem[];
    constexpr int L = (CIN == 128) ? 54 : 27;
    const u32 sb = smem_u32(smem);
    const int tid = threadIdx.x, w = tid >> 5, lane = tid & 31;
    const int x = blockIdx.x, y0 = blockIdx.y * 4, b = blockIdx.z;

    const __half* in = (CIN == 64) ? g_g0 : g_h1;
    const __half* wp = (CIN == 64) ? g_w1 : g_w2;

    float acc[16][4];
#pragma unroll
    for (int n = 0; n < 16; n++)
#pragma unroll
        for (int j = 0; j < 4; j++) acc[n][j] = 0.f;

    load_chunk<CIN>(0, 0, sb, tid, b, x, y0, in, wp);

#pragma unroll 1
    for (int c = 0; c < L; c++) {
        asm volatile("cp.async.wait_group 0;" ::: "memory");
        __syncthreads();
        if (c + 1 < L)
            load_chunk<CIN>(c + 1, (c + 1) & 1, sb, tid, b, x, y0, in, wp);

        const u32 abase = sb + (c & 1) * BUF_SZ;
        const u32 a_addr0 = abase + (w * 16 + (lane & 15)) * PITCH + (lane >> 4) * 16;
        const u32 b_row = (lane & 7) + ((lane >> 3) & 1) * 8;
        const u32 b_addr0 = abase + TEN_SZ + b_row * PITCH + (lane >> 4) * 16;
#pragma unroll
        for (int ks = 0; ks < 4; ks++) {
            u32 ah0, ah1, ah2, ah3;
            ldsm4(ah0, ah1, ah2, ah3, a_addr0 + ks * 32);
#pragma unroll
            for (int ng = 0; ng < 8; ng++) {
                u32 wh0, wh1, wh2, wh3;
                ldsm4(wh0, wh1, wh2, wh3, b_addr0 + ng * 16 * PITCH + ks * 32);
                float* d0 = acc[2 * ng];
                float* d1 = acc[2 * ng + 1];
                mma16816(d0[0], d0[1], d0[2], d0[3], ah0, ah1, ah2, ah3, wh0, wh2);
                mma16816(d1[0], d1[1], d1[2], d1[3], ah0, ah1, ah2, ah3, wh1, wh3);
            }
        }
        __syncthreads();
    }

    // ---- epilogue: bias + per-voxel GN(16 ch) + SiLU, straight from fragments ----
    const int r0 = lane >> 2, cq = lane & 3;
#pragma unroll
    for (int h = 0; h < 2; h++) {
        int row_m = w * 16 + r0 + h * 8;
        int yl = row_m >> 5, z = row_m & 31;
        size_t vox = (((size_t)(b * 32 + x)) * 32 + (y0 + yl)) * 32 + z;
#pragma unroll
        for (int g = 0; g < 8; g++) {
            float v[4];
            int cA = g * 16 + cq * 2;
            int cB = g * 16 + 8 + cq * 2;
            v[0] = acc[2 * g][2 * h + 0]     + bias[cA + 0];
            v[1] = acc[2 * g][2 * h + 1]     + bias[cA + 1];
            v[2] = acc[2 * g + 1][2 * h + 0] + bias[cB + 0];
            v[3] = acc[2 * g + 1][2 * h + 1] + bias[cB + 1];
            float s = v[0] + v[1] + v[2] + v[3];
            float q = v[0] * v[0] + v[1] * v[1] + v[2] * v[2] + v[3] * v[3];
            s += __shfl_xor_sync(0xffffffffu, s, 1);
            s += __shfl_xor_sync(0xffffffffu, s, 2);
            q += __shfl_xor_sync(0xffffffffu, q, 1);
            q += __shfl_xor_sync(0xffffffffu, q, 2);
            float mu  = s * (1.0f / 16.0f);
            float var = q * (1.0f / 16.0f) - mu * mu;
            float rs  = rsqrtf(var + 1e-5f);
            float y2[4];
#pragma unroll
            for (int j = 0; j < 4; j++) {
                int col = (j < 2) ? (cA + j) : (cB + (j - 2));
                float y = (v[j] - mu) * rs * gamma[col] + beta[col];
                y2[j] = y / (1.0f + expf(-y));
            }
            if (CIN == 64) {
                __half2 hA; hA.x = __float2half_rn(y2[0]); hA.y = __float2half_rn(y2[1]);
                __half2 hB; hB.x = __float2half_rn(y2[2]); hB.y = __float2half_rn(y2[3]);
                *(__half2*)&g_h1[vox * COUT + cA] = hA;
                *(__half2*)&g_h1[vox * COUT + cB] = hB;
            } else {
                *(float2*)&g_h2[vox * COUT + cA] = make_float2(y2[0], y2[1]);
                *(float2*)&g_h2[vox * COUT + cB] = make_float2(y2[2], y2[3]);
            }
        }
    }
}

// ---------------- point branch GEMM + global group stats ------------------------
__global__ void __launch_bounds__(128)
mlp_gstats_kernel(const float* __restrict__ feats,
                  const float* __restrict__ w,
                  const float* __restrict__ bias) {
    __shared__ float s_w[CIN0 * 129];
    __shared__ float s_f[CIN0 * 32];
    const int tid = threadIdx.x;
    const int b   = blockIdx.x >> 9;
    const int n0  = (blockIdx.x & 511) * 32;

    for (int i = tid; i < COUT * CIN0; i += 128) {
        int c = i >> 6, ci = i & 63;
        s_w[ci * 129 + c] = w[i];
    }
    for (int i = tid; i < CIN0 * 32; i += 128) {
        int ci = i >> 5, p = i & 31;
        s_f[ci * 32 + p] = feats[((size_t)b * CIN0 + ci) * NN + n0 + p];
    }
    __syncthreads();

    const int c = tid;
    float bv = bias[c];
    float lsum = 0.f, lsq = 0.f;
    for (int p = 0; p < 32; p++) {
        float a = bv;
#pragma unroll 16
        for (int ci = 0; ci < CIN0; ci++)
            a += s_w[ci * 129 + c] * s_f[ci * 32 + p];
        g_pf[((size_t)b * NN + n0 + p) * COUT + c] = a;
        lsum += a; lsq += a * a;
    }
#pragma unroll
    for (int o = 8; o >= 1; o >>= 1) {
        lsum += __shfl_xor_sync(0xffffffffu, lsum, o, 16);
        lsq  += __shfl_xor_sync(0xffffffffu, lsq,  o, 16);
    }
    if ((tid & 15) == 0) {
        int g = c >> 4;
        atomicAdd(&g_stats[(b * 8 + g) * 2 + 0], lsum);
        atomicAdd(&g_stats[(b * 8 + g) * 2 + 1], lsq);
    }
}

__global__ void stats_finalize_kernel() {
    int t = threadIdx.x;
    if (t >= BB * 8) return;
    const float inv = 1.0f / (16.0f * (float)NN);
    float s = g_stats[t * 2 + 0], s2 = g_stats[t * 2 + 1];
    float mu = s * inv;
    float var = s2 * inv - mu * mu;
    g_stats[t * 2 + 0] = mu;
    g_stats[t * 2 + 1] = rsqrtf(var + 1e-5f);
}

// ---------------- devoxelize + point GN/SiLU + add ------------------------------
__global__ void __launch_bounds__(128)
devox_out_kernel(const float* __restrict__ coords,
                 const float* __restrict__ gamma,
                 const float* __restrict__ beta,
                 float* __restrict__ out) {
    __shared__ float s_o[COUT * 17];
    const int c  = threadIdx.x;
    const int p0 = blockIdx.x * 16;
    const int b  = p0 >> 14;
    const int n0 = p0 & (NN - 1);
    const int g  = c >> 4;
    const float gm = gamma[c], bt = beta[c];
    const float mu = g_stats[(b * 8 + g) * 2 + 0];
    const float rs = g_stats[(b * 8 + g) * 2 + 1];

    for (int p = 0; p < 16; p++) {
        int gp = p0 + p;
        float cx = coords[gp * 3 + 0] * (float)RR;
        float cy = coords[gp * 3 + 1] * (float)RR;
        float cz = coords[gp * 3 + 2] * (float)RR;
        float fxl = floorf(cx), fyl = floorf(cy), fzl = floorf(cz);
        int ix = min(max((int)fxl, 0), RR - 1);
        int iy = min(max((int)fyl, 0), RR - 1);
        int iz = min(max((int)fzl, 0), RR - 1);
        int hx = min(ix + 1, RR - 1), hy = min(iy + 1, RR - 1), hz = min(iz + 1, RR - 1);
        float fx = cx - fxl, fy = cy - fyl, fz = cz - fzl;

        float v = 0.f;
#pragma unroll
        for (int dx = 0; dx < 2; dx++) {
            float wx = dx ? fx : 1.f - fx;
            int X = dx ? hx : ix;
#pragma unroll
            for (int dy = 0; dy < 2; dy++) {
                float wy = dy ? fy : 1.f - fy;
                int Y = dy ? hy : iy;
#pragma unroll
                for (int dz = 0; dz < 2; dz++) {
                    float wz = dz ? fz : 1.f - fz;
                    int Z = dz ? hz : iz;
                    size_t base = (((size_t)(b * RR + X) * RR + Y) * RR + Z) * COUT + c;
                    v += (wx * wy * wz) * g_h2[base];
                }
            }
        }
        float pv = g_pf[((size_t)gp) * COUT + c];
        float y  = (pv - mu) * rs * gm + bt;
        y = y / (1.0f + expf(-y));
        s_o[c * 17 + p] = v + y;
    }
    __syncthreads();
    for (int i = threadIdx.x; i < COUT * 16; i += 128) {
        int c2 = i >> 4, p = i & 15;
        out[((size_t)b * COUT + c2) * NN + n0 + p] = s_o[c2 * 17 + p];
    }
}

// ---------------- launch ----------------------------------------------------------
extern "C" void kernel_launch(void* const* d_in, const int* in_sizes, int n_in,
                              void* d_out, int out_size) {
    const float* coords   = (const float*)d_in[0];
    const float* features = (const float*)d_in[1];
    const float* conv1_w  = (const float*)d_in[2];
    const float* conv1_b  = (const float*)d_in[3];
    const float* gn1_g    = (const float*)d_in[4];
    const float* gn1_b    = (const float*)d_in[5];
    const float* conv2_w  = (const float*)d_in[6];
    const float* conv2_b  = (const float*)d_in[7];
    const float* gn2_g    = (const float*)d_in[8];
    const float* gn2_b    = (const float*)d_in[9];
    const float* mlp_w    = (const float*)d_in[10];
    const float* mlp_b    = (const float*)d_in[11];
    const float* gnp_g    = (const float*)d_in[12];
    const float* gnp_b    = (const float*)d_in[13];
    float* out = (float*)d_out;

    static int attr_done = 0;
    if (!attr_done) {
        cudaFuncSetAttribute(conv_mma_kernel<CIN0>,
                             cudaFuncAttributeMaxDynamicSharedMemorySize, CVSMEM);
        cudaFuncSetAttribute(conv_mma_kernel<COUT>,
                             cudaFuncAttributeMaxDynamicSharedMemorySize, CVSMEM);
        attr_done = 1;
    }

    zero_scratch_kernel<<<2048, 256>>>();
    wprep_kernel<CIN0><<<(COUT * CIN0 * 27 + 255) / 256, 256>>>(conv1_w);
    wprep_kernel<COUT><<<(COUT * COUT * 27 + 255) / 256, 256>>>(conv2_w);

    scatter_kernel<<<(BB * NN * CIN0 + 255) / 256, 256>>>(coords, features);
    vox_split_kernel<<<4096, 256>>>();

    dim3 cgrid(RR, 8, BB);   // x, y-tile, b
    conv_mma_kernel<CIN0><<<cgrid, 256, CVSMEM>>>(conv1_b, gn1_g, gn1_b);
    conv_mma_kernel<COUT><<<cgrid, 256, CVSMEM>>>(conv2_b, gn2_g, gn2_b);

    mlp_gstats_kernel<<<BB * (NN / 32), 128>>>(features, mlp_w, mlp_b);
    stats_finalize_kernel<<<1, 32>>>();

    devox_out_kernel<<<BB * NN / 16, 128>>>(coords, gnp_g, gnp_b, out);
}

// round 8
// speedup vs baseline: 1.9066x; 1.0128x over previous
#include <cuda_runtime.h>
#include <cuda_fp16.h>
#include <math.h>
#include <stdint.h>

#define BB   4
#define NN   16384
#define CIN0 64
#define COUT 128
#define RR   32
#define NVOX (BB*RR*RR*RR)   /* 131072 */

typedef unsigned int u32;
typedef unsigned long long u64;

// ---------------- scratch (device globals) ------------------------------------
__device__ float g_grid[(size_t)NVOX * CIN0];
__device__ float g_cnt [NVOX];
__device__ __align__(16) __half g_g0[(size_t)NVOX * CIN0];    // conv1 in (fp16)
__device__ __align__(16) __half g_h1[(size_t)NVOX * COUT];    // conv2 in (fp16)
__device__ float g_h2  [(size_t)NVOX * COUT];
__device__ float g_pf  [(size_t)BB * NN * COUT];
__device__ float g_stats[BB * 8 * 2];
__device__ __align__(16) __half g_w1[27 * COUT * CIN0];       // [tap][co][ci] fp16
__device__ __align__(16) __half g_w2[27 * COUT * COUT];

// ---------------- helpers -------------------------------------------------------
__device__ __forceinline__ u32 smem_u32(const void* p) {
    u32 a;
    asm("{ .reg .u64 t; cvta.to.shared.u64 t, %1; cvt.u32.u64 %0, t; }" : "=r"(a) : "l"(p));
    return a;
}
__device__ __forceinline__ void cp16(u32 dst, const void* src, u32 sz) {
    asm volatile("cp.async.cg.shared.global [%0], [%1], 16, %2;"
                 :: "r"(dst), "l"(src), "r"(sz) : "memory");
}
__device__ __forceinline__ void ldsm4(u32& r0, u32& r1, u32& r2, u32& r3, u32 a) {
    asm volatile("ldmatrix.sync.aligned.m8n8.x4.shared.b16 {%0,%1,%2,%3}, [%4];"
                 : "=r"(r0), "=r"(r1), "=r"(r2), "=r"(r3) : "r"(a));
}
__device__ __forceinline__ void mma16816(float* d,
                                         u32 a0, u32 a1, u32 a2, u32 a3,
                                         u32 b0, u32 b1) {
    asm volatile("mma.sync.aligned.m16n8k16.row.col.f32.f16.f16.f32 "
                 "{%0,%1,%2,%3}, {%4,%5,%6,%7}, {%8,%9}, {%0,%1,%2,%3};"
                 : "+f"(d[0]), "+f"(d[1]), "+f"(d[2]), "+f"(d[3])
                 : "r"(a0), "r"(a1), "r"(a2), "r"(a3), "r"(b0), "r"(b1));
}

// ---------------- zero scratch --------------------------------------------------
__global__ void zero_scratch_kernel() {
    const long NG = (long)NVOX * CIN0, NC = NVOX, NS = BB * 8 * 2;
    const long total = NG + NC + NS;
    for (long i = (long)blockIdx.x * blockDim.x + threadIdx.x; i < total;
         i += (long)gridDim.x * blockDim.x) {
        if (i < NG)            g_grid[i] = 0.f;
        else if (i < NG + NC)  g_cnt[i - NG] = 0.f;
        else                   g_stats[i - NG - NC] = 0.f;
    }
}

// ---- weight prep: w[co][ci][tap] -> [tap][co][ci] fp16 --------------------------
template <int CIN>
__global__ void wprep_kernel(const float* __restrict__ w) {
    __half* dst = (CIN == CIN0) ? g_w1 : g_w2;
    int total = COUT * CIN * 27;
    for (int i = blockIdx.x * blockDim.x + threadIdx.x; i < total;
         i += gridDim.x * blockDim.x) {
        int co  = i / (CIN * 27);
        int r   = i - co * (CIN * 27);
        int ci  = r / 27;
        int tap = r - ci * 27;
        dst[(tap * COUT + co) * CIN + ci] = __float2half_rn(w[i]);
    }
}

// ---------------- voxelize -------------------------------------------------------
__global__ void scatter_kernel(const float* __restrict__ coords,
                               const float* __restrict__ feats) {
    int idx = blockIdx.x * blockDim.x + threadIdx.x;
    if (idx >= BB * NN * CIN0) return;
    int ci = idx & (CIN0 - 1);
    int gp = idx >> 6;
    int b  = gp >> 14;
    int n  = gp & (NN - 1);
    float cx = coords[gp * 3 + 0] * (float)RR;
    float cy = coords[gp * 3 + 1] * (float)RR;
    float cz = coords[gp * 3 + 2] * (float)RR;
    int ix = min(max((int)floorf(cx), 0), RR - 1);
    int iy = min(max((int)floorf(cy), 0), RR - 1);
    int iz = min(max((int)floorf(cz), 0), RR - 1);
    int vox = ((b * RR + ix) * RR + iy) * RR + iz;
    atomicAdd(&g_grid[(size_t)vox * CIN0 + ci],
              feats[((size_t)b * CIN0 + ci) * NN + n]);
    if (ci == 0) atomicAdd(&g_cnt[vox], 1.0f);
}

__global__ void vox_split_kernel() {
    long total = (long)NVOX * CIN0;
    for (long i = (long)blockIdx.x * blockDim.x + threadIdx.x; i < total;
         i += (long)gridDim.x * blockDim.x) {
        long v = i >> 6;
        float c = g_cnt[v];
        float val = g_grid[i] * (1.0f / fmaxf(c, 1.0f));
        g_g0[i] = __float2half_rn(val);
    }
}

// ---------------- mma.sync conv (fp16) + GN + SiLU ------------------------------
// CTA: (b, x-pair) slab: 2x x 4y x 32z = M256 rows; N=128 couts; K-chunk = 64.
// 8 warps as 4M x 2N: warp tile M64 x N64 (acc 128 fp32/thread).
// Buffers: A 256x128B + W 128x128B @ pitch 144B, double-buffered (108 KB).
#define PITCH   144
#define ATEN    (256 * PITCH)        /* 36864 */
#define WTEN    (128 * PITCH)        /* 18432 */
#define BUF_SZ  (ATEN + WTEN)        /* 55296 */
#define CVSMEM  (2 * BUF_SZ)         /* 110592 */

template <int CIN>
__device__ __forceinline__ void load_chunk(
    int c, int buf, u32 sb, int tid, int b, int x0, int y0,
    const __half* in, const __half* wp) {
    const int tap = (CIN == 128) ? (c >> 1) : c;
    const int ci0 = (CIN == 128) ? ((c & 1) * 64) : 0;
    const int dx = tap / 9, dy = (tap / 3) % 3, dz = tap % 3;
    const u32 base = sb + buf * BUF_SZ;
#pragma unroll
    for (int i = 0; i < 12; i++) {
        int unit = tid + i * 256;            // 3072 units of 16B
        if (unit < 2048) {                   // A: 256 rows x 8 units
            int row = unit >> 3, c16 = unit & 7;
            int xl = row >> 7, yl = (row >> 5) & 3, z = row & 31;
            int gx = x0 + xl + dx - 1;
            int gy = y0 + yl + dy - 1;
            int gz = z + dz - 1;
            bool ok = ((unsigned)gx < 32u) & ((unsigned)gy < 32u) & ((unsigned)gz < 32u);
            size_t off = 0;
            if (ok)
                off = ((((size_t)(b * 32 + gx)) * 32 + gy) * 32 + gz) * CIN + ci0 + c16 * 8;
            cp16(base + row * PITCH + c16 * 16, in + off, ok ? 16u : 0u);
        } else {                             // W: 128 rows x 8 units
            int wu = unit - 2048;
            int row = wu >> 3, c16 = wu & 7;
            size_t off = ((size_t)tap * COUT + row) * CIN + ci0 + c16 * 8;
            cp16(base + ATEN + row * PITCH + c16 * 16, wp + off, 16u);
        }
    }
    asm volatile("cp.async.commit_group;" ::: "memory");
}

template <int CIN>
__global__ void __launch_bounds__(256, 1)
conv_mma_kernel(const float* __restrict__ bias,
                const float* __restrict__ gamma,
                const float* __restrict__ beta) {
    extern __shared__ __align__(128) char smem[];
    constexpr int L = (CIN == 128) ? 54 : 27;
    const u32 sb = smem_u32(smem);
    const int tid = threadIdx.x, w = tid >> 5, lane = tid & 31;
    const int x0 = blockIdx.x * 2, y0 = blockIdx.y * 4, b = blockIdx.z;
    const int wM = w >> 1, wN = w & 1;

    const __half* in = (CIN == 64) ? g_g0 : g_h1;
    const __half* wp = (CIN == 64) ? g_w1 : g_w2;

    float acc[4][8][4];                      // [m-tile][n8][frag]
#pragma unroll
    for (int mt = 0; mt < 4; mt++)
#pragma unroll
        for (int nn = 0; nn < 8; nn++)
#pragma unroll
            for (int j = 0; j < 4; j++) acc[mt][nn][j] = 0.f;

    load_chunk<CIN>(0, 0, sb, tid, b, x0, y0, in, wp);

    const u32 a_off = (wM * 64 + (lane & 15)) * PITCH + (lane >> 4) * 16;
    const u32 b_row = (lane & 7) + ((lane >> 3) & 1) * 8;
    const u32 b_off = ATEN + (wN * 64 + b_row) * PITCH + (lane >> 4) * 16;

#pragma unroll 1
    for (int c = 0; c < L; c++) {
        asm volatile("cp.async.wait_group 0;" ::: "memory");
        __syncthreads();
        if (c + 1 < L)
            load_chunk<CIN>(c + 1, (c + 1) & 1, sb, tid, b, x0, y0, in, wp);

        const u32 abase = sb + (c & 1) * BUF_SZ;
#pragma unroll
        for (int ks = 0; ks < 4; ks++) {
            u32 a[4][4];
#pragma unroll
            for (int mt = 0; mt < 4; mt++)
                ldsm4(a[mt][0], a[mt][1], a[mt][2], a[mt][3],
                      abase + a_off + mt * 16 * PITCH + ks * 32);
#pragma unroll
            for (int nt = 0; nt < 4; nt++) {
                u32 w0, w1, w2, w3;
                ldsm4(w0, w1, w2, w3, abase + b_off + nt * 16 * PITCH + ks * 32);
#pragma unroll
                for (int mt = 0; mt < 4; mt++) {
                    mma16816(acc[mt][2 * nt],     a[mt][0], a[mt][1], a[mt][2], a[mt][3], w0, w2);
                    mma16816(acc[mt][2 * nt + 1], a[mt][0], a[mt][1], a[mt][2], a[mt][3], w1, w3);
                }
            }
        }
        __syncthreads();
    }

    // ---- epilogue: bias + per-voxel GN(16 ch) + SiLU, straight from fragments ----
    const int r0 = lane >> 2, cq = lane & 3;
#pragma unroll
    for (int mt = 0; mt < 4; mt++) {
#pragma unroll
        for (int h = 0; h < 2; h++) {
            int row_m = wM * 64 + mt * 16 + r0 + h * 8;
            int xl = row_m >> 7, yl = (row_m >> 5) & 3, z = row_m & 31;
            size_t vox = (((size_t)(b * 32 + x0 + xl)) * 32 + (y0 + yl)) * 32 + z;
#pragma unroll
            for (int k = 0; k < 4; k++) {
                int cA = wN * 64 + k * 16 + cq * 2;
                int cB = cA + 8;
                float v[4];
                v[0] = acc[mt][2 * k][2 * h + 0]     + bias[cA + 0];
                v[1] = acc[mt][2 * k][2 * h + 1]     + bias[cA + 1];
                v[2] = acc[mt][2 * k + 1][2 * h + 0] + bias[cB + 0];
                v[3] = acc[mt][2 * k + 1][2 * h + 1] + bias[cB + 1];
                float s = v[0] + v[1] + v[2] + v[3];
                float q = v[0] * v[0] + v[1] * v[1] + v[2] * v[2] + v[3] * v[3];
                s += __shfl_xor_sync(0xffffffffu, s, 1);
                s += __shfl_xor_sync(0xffffffffu, s, 2);
                q += __shfl_xor_sync(0xffffffffu, q, 1);
                q += __shfl_xor_sync(0xffffffffu, q, 2);
                float mu  = s * (1.0f / 16.0f);
                float var = q * (1.0f / 16.0f) - mu * mu;
                float rs  = rsqrtf(var + 1e-5f);
                float y2[4];
#pragma unroll
                for (int j = 0; j < 4; j++) {
                    int col = (j < 2) ? (cA + j) : (cB + (j - 2));
                    float y = (v[j] - mu) * rs * gamma[col] + beta[col];
                    y2[j] = y / (1.0f + expf(-y));
                }
                if (CIN == 64) {
                    __half2 hA; hA.x = __float2half_rn(y2[0]); hA.y = __float2half_rn(y2[1]);
                    __half2 hB; hB.x = __float2half_rn(y2[2]); hB.y = __float2half_rn(y2[3]);
                    *(__half2*)&g_h1[vox * COUT + cA] = hA;
                    *(__half2*)&g_h1[vox * COUT + cB] = hB;
                } else {
                    *(float2*)&g_h2[vox * COUT + cA] = make_float2(y2[0], y2[1]);
                    *(float2*)&g_h2[vox * COUT + cB] = make_float2(y2[2], y2[3]);
                }
            }
        }
    }
}

// ---------------- point branch GEMM + global group stats ------------------------
__global__ void __launch_bounds__(128)
mlp_gstats_kernel(const float* __restrict__ feats,
                  const float* __restrict__ w,
                  const float* __restrict__ bias) {
    __shared__ float s_w[CIN0 * 129];
    __shared__ float s_f[CIN0 * 32];
    const int tid = threadIdx.x;
    const int b   = blockIdx.x >> 9;
    const int n0  = (blockIdx.x & 511) * 32;

    for (int i = tid; i < COUT * CIN0; i += 128) {
        int c = i >> 6, ci = i & 63;
        s_w[ci * 129 + c] = w[i];
    }
    for (int i = tid; i < CIN0 * 32; i += 128) {
        int ci = i >> 5, p = i & 31;
        s_f[ci * 32 + p] = feats[((size_t)b * CIN0 + ci) * NN + n0 + p];
    }
    __syncthreads();

    const int c = tid;
    float bv = bias[c];
    float lsum = 0.f, lsq = 0.f;
    for (int p = 0; p < 32; p++) {
        float a = bv;
#pragma unroll 16
        for (int ci = 0; ci < CIN0; ci++)
            a += s_w[ci * 129 + c] * s_f[ci * 32 + p];
        g_pf[((size_t)b * NN + n0 + p) * COUT + c] = a;
        lsum += a; lsq += a * a;
    }
#pragma unroll
    for (int o = 8; o >= 1; o >>= 1) {
        lsum += __shfl_xor_sync(0xffffffffu, lsum, o, 16);
        lsq  += __shfl_xor_sync(0xffffffffu, lsq,  o, 16);
    }
    if ((tid & 15) == 0) {
        int g = c >> 4;
        atomicAdd(&g_stats[(b * 8 + g) * 2 + 0], lsum);
        atomicAdd(&g_stats[(b * 8 + g) * 2 + 1], lsq);
    }
}

__global__ void stats_finalize_kernel() {
    int t = threadIdx.x;
    if (t >= BB * 8) return;
    const float inv = 1.0f / (16.0f * (float)NN);
    float s = g_stats[t * 2 + 0], s2 = g_stats[t * 2 + 1];
    float mu = s * inv;
    float var = s2 * inv - mu * mu;
    g_stats[t * 2 + 0] = mu;
    g_stats[t * 2 + 1] = rsqrtf(var + 1e-5f);
}

// ---------------- devoxelize + point GN/SiLU + add ------------------------------
__global__ void __launch_bounds__(128)
devox_out_kernel(const float* __restrict__ coords,
                 const float* __restrict__ gamma,
                 const float* __restrict__ beta,
                 float* __restrict__ out) {
    __shared__ float s_o[COUT * 17];
    const int c  = threadIdx.x;
    const int p0 = blockIdx.x * 16;
    const int b  = p0 >> 14;
    const int n0 = p0 & (NN - 1);
    const int g  = c >> 4;
    const float gm = gamma[c], bt = beta[c];
    const float mu = g_stats[(b * 8 + g) * 2 + 0];
    const float rs = g_stats[(b * 8 + g) * 2 + 1];

    for (int p = 0; p < 16; p++) {
        int gp = p0 + p;
        float cx = coords[gp * 3 + 0] * (float)RR;
        float cy = coords[gp * 3 + 1] * (float)RR;
        float cz = coords[gp * 3 + 2] * (float)RR;
        float fxl = floorf(cx), fyl = floorf(cy), fzl = floorf(cz);
        int ix = min(max((int)fxl, 0), RR - 1);
        int iy = min(max((int)fyl, 0), RR - 1);
        int iz = min(max((int)fzl, 0), RR - 1);
        int hx = min(ix + 1, RR - 1), hy = min(iy + 1, RR - 1), hz = min(iz + 1, RR - 1);
        float fx = cx - fxl, fy = cy - fyl, fz = cz - fzl;

        float v = 0.f;
#pragma unroll
        for (int dx = 0; dx < 2; dx++) {
            float wx = dx ? fx : 1.f - fx;
            int X = dx ? hx : ix;
#pragma unroll
            for (int dy = 0; dy < 2; dy++) {
                float wy = dy ? fy : 1.f - fy;
                int Y = dy ? hy : iy;
#pragma unroll
                for (int dz = 0; dz < 2; dz++) {
                    float wz = dz ? fz : 1.f - fz;
                    int Z = dz ? hz : iz;
                    size_t base = (((size_t)(b * RR + X) * RR + Y) * RR + Z) * COUT + c;
                    v += (wx * wy * wz) * g_h2[base];
                }
            }
        }
        float pv = g_pf[((size_t)gp) * COUT + c];
        float y  = (pv - mu) * rs * gm + bt;
        y = y / (1.0f + expf(-y));
        s_o[c * 17 + p] = v + y;
    }
    __syncthreads();
    for (int i = threadIdx.x; i < COUT * 16; i += 128) {
        int c2 = i >> 4, p = i & 15;
        out[((size_t)b * COUT + c2) * NN + n0 + p] = s_o[c2 * 17 + p];
    }
}

// ---------------- launch ----------------------------------------------------------
extern "C" void kernel_launch(void* const* d_in, const int* in_sizes, int n_in,
                              void* d_out, int out_size) {
    const float* coords   = (const float*)d_in[0];
    const float* features = (const float*)d_in[1];
    const float* conv1_w  = (const float*)d_in[2];
    const float* conv1_b  = (const float*)d_in[3];
    const float* gn1_g    = (const float*)d_in[4];
    const float* gn1_b    = (const float*)d_in[5];
    const float* conv2_w  = (const float*)d_in[6];
    const float* conv2_b  = (const float*)d_in[7];
    const float* gn2_g    = (const float*)d_in[8];
    const float* gn2_b    = (const float*)d_in[9];
    const float* mlp_w    = (const float*)d_in[10];
    const float* mlp_b    = (const float*)d_in[11];
    const float* gnp_g    = (const float*)d_in[12];
    const float* gnp_b    = (const float*)d_in[13];
    float* out = (float*)d_out;

    static int attr_done = 0;
    if (!attr_done) {
        cudaFuncSetAttribute(conv_mma_kernel<CIN0>,
                             cudaFuncAttributeMaxDynamicSharedMemorySize, CVSMEM);
        cudaFuncSetAttribute(conv_mma_kernel<COUT>,
                             cudaFuncAttributeMaxDynamicSharedMemorySize, CVSMEM);
        attr_done = 1;
    }

    zero_scratch_kernel<<<2048, 256>>>();
    wprep_kernel<CIN0><<<(COUT * CIN0 * 27 + 255) / 256, 256>>>(conv1_w);
    wprep_kernel<COUT><<<(COUT * COUT * 27 + 255) / 256, 256>>>(conv2_w);

    scatter_kernel<<<(BB * NN * CIN0 + 255) / 256, 256>>>(coords, features);
    vox_split_kernel<<<4096, 256>>>();

    dim3 cgrid(RR / 2, 8, BB);   // x-pair, y-tile, b
    conv_mma_kernel<CIN0><<<cgrid, 256, CVSMEM>>>(conv1_b, gn1_g, gn1_b);
    conv_mma_kernel<COUT><<<cgrid, 256, CVSMEM>>>(conv2_b, gn2_g, gn2_b);

    mlp_gstats_kernel<<<BB * (NN / 32), 128>>>(features, mlp_w, mlp_b);
    stats_finalize_kernel<<<1, 32>>>();

    devox_out_kernel<<<BB * NN / 16, 128>>>(coords, gnp_g, gnp_b, out);
}

// round 9
// speedup vs baseline: 2.2406x; 1.1752x over previous
#include <cuda_runtime.h>
#include <cuda_fp16.h>
#include <math.h>
#include <stdint.h>

#define BB   4
#define NN   16384
#define CIN0 64
#define COUT 128
#define RR   32
#define NVOX (BB*RR*RR*RR)   /* 131072 */

typedef unsigned int u32;
typedef unsigned long long u64;

// ---------------- scratch (device globals) ------------------------------------
__device__ float g_grid[(size_t)NVOX * CIN0];
__device__ float g_cnt [NVOX];
__device__ __align__(16) __half g_g0[(size_t)NVOX * CIN0];    // conv1 in (fp16)
__device__ __align__(16) __half g_h1[(size_t)NVOX * COUT];    // conv2 in (fp16)
__device__ float g_h2  [(size_t)NVOX * COUT];
__device__ float g_pf  [(size_t)BB * NN * COUT];
__device__ float g_stats[BB * 8 * 2];
// W layouts: conv1 [tap][co][ci64]; conv2 [ci-half][tap][co][ci64]
__device__ __align__(16) __half g_w1[27 * COUT * 64];
__device__ __align__(16) __half g_w2[2 * 27 * COUT * 64];

// ---------------- helpers -------------------------------------------------------
__device__ __forceinline__ u32 smem_u32(const void* p) {
    u32 a;
    asm("{ .reg .u64 t; cvta.to.shared.u64 t, %1; cvt.u32.u64 %0, t; }" : "=r"(a) : "l"(p));
    return a;
}
__device__ __forceinline__ void cp16(u32 dst, const void* src, u32 sz) {
    asm volatile("cp.async.cg.shared.global [%0], [%1], 16, %2;"
                 :: "r"(dst), "l"(src), "r"(sz) : "memory");
}
__device__ __forceinline__ void ldsm4(u32& r0, u32& r1, u32& r2, u32& r3, u32 a) {
    asm volatile("ldmatrix.sync.aligned.m8n8.x4.shared.b16 {%0,%1,%2,%3}, [%4];"
                 : "=r"(r0), "=r"(r1), "=r"(r2), "=r"(r3) : "r"(a));
}
__device__ __forceinline__ void mma16816(float* d,
                                         u32 a0, u32 a1, u32 a2, u32 a3,
                                         u32 b0, u32 b1) {
    asm volatile("mma.sync.aligned.m16n8k16.row.col.f32.f16.f16.f32 "
                 "{%0,%1,%2,%3}, {%4,%5,%6,%7}, {%8,%9}, {%0,%1,%2,%3};"
                 : "+f"(d[0]), "+f"(d[1]), "+f"(d[2]), "+f"(d[3])
                 : "r"(a0), "r"(a1), "r"(a2), "r"(a3), "r"(b0), "r"(b1));
}

// ---------------- zero scratch --------------------------------------------------
__global__ void zero_scratch_kernel() {
    const long NG = (long)NVOX * CIN0, NC = NVOX, NS = BB * 8 * 2;
    const long total = NG + NC + NS;
    for (long i = (long)blockIdx.x * blockDim.x + threadIdx.x; i < total;
         i += (long)gridDim.x * blockDim.x) {
        if (i < NG)            g_grid[i] = 0.f;
        else if (i < NG + NC)  g_cnt[i - NG] = 0.f;
        else                   g_stats[i - NG - NC] = 0.f;
    }
}

// ---- weight prep ----------------------------------------------------------------
// conv1: w[co][ci][tap] -> g_w1[(tap*128 + co)*64 + ci]
__global__ void wprep1_kernel(const float* __restrict__ w) {
    int total = COUT * 64 * 27;
    for (int i = blockIdx.x * blockDim.x + threadIdx.x; i < total;
         i += gridDim.x * blockDim.x) {
        int co  = i / (64 * 27);
        int r   = i - co * (64 * 27);
        int ci  = r / 27;
        int tap = r - ci * 27;
        g_w1[(tap * COUT + co) * 64 + ci] = __float2half_rn(w[i]);
    }
}
// conv2: w[co][ci][tap] -> g_w2[(((ci>>6)*27 + tap)*128 + co)*64 + (ci&63)]
__global__ void wprep2_kernel(const float* __restrict__ w) {
    int total = COUT * 128 * 27;
    for (int i = blockIdx.x * blockDim.x + threadIdx.x; i < total;
         i += gridDim.x * blockDim.x) {
        int co  = i / (128 * 27);
        int r   = i - co * (128 * 27);
        int ci  = r / 27;
        int tap = r - ci * 27;
        g_w2[((((ci >> 6) * 27) + tap) * COUT + co) * 64 + (ci & 63)] =
            __float2half_rn(w[i]);
    }
}

// ---------------- voxelize -------------------------------------------------------
__global__ void scatter_kernel(const float* __restrict__ coords,
                               const float* __restrict__ feats) {
    int idx = blockIdx.x * blockDim.x + threadIdx.x;
    if (idx >= BB * NN * CIN0) return;
    int ci = idx & (CIN0 - 1);
    int gp = idx >> 6;
    int b  = gp >> 14;
    int n  = gp & (NN - 1);
    float cx = coords[gp * 3 + 0] * (float)RR;
    float cy = coords[gp * 3 + 1] * (float)RR;
    float cz = coords[gp * 3 + 2] * (float)RR;
    int ix = min(max((int)floorf(cx), 0), RR - 1);
    int iy = min(max((int)floorf(cy), 0), RR - 1);
    int iz = min(max((int)floorf(cz), 0), RR - 1);
    int vox = ((b * RR + ix) * RR + iy) * RR + iz;
    atomicAdd(&g_grid[(size_t)vox * CIN0 + ci],
              feats[((size_t)b * CIN0 + ci) * NN + n]);
    if (ci == 0) atomicAdd(&g_cnt[vox], 1.0f);
}

__global__ void vox_split_kernel() {
    long total = (long)NVOX * CIN0;
    for (long i = (long)blockIdx.x * blockDim.x + threadIdx.x; i < total;
         i += (long)gridDim.x * blockDim.x) {
        long v = i >> 6;
        float c = g_cnt[v];
        float val = g_grid[i] * (1.0f / fmaxf(c, 1.0f));
        g_g0[i] = __float2half_rn(val);
    }
}

// ---------------- mma.sync conv (fp16) + GN + SiLU ------------------------------
// CTA: (b, 2x, 4y, 32z) = M256 rows x N128 couts. 8 warps 4M x 2N (warp M64xN64).
// A halo plane resident in smem: 4x x 6y x 34z = 816 rows x 128B (one ci-half),
// loaded ONCE per ci-half (6528 cp.async). W streamed per tap (1024 cp.async),
// double-buffered. Per-tap shift applied via LDSM addressing.
#define PITCH    144
#define APLANE   (816 * PITCH)       /* 117504 */
#define WTEN     (128 * PITCH)       /* 18432  */
#define CVSMEM   (APLANE + 2 * WTEN) /* 154368 */

template <int CIN>
__device__ __forceinline__ void load_Aplane(
    int h, u32 sb, int tid, int b, int x0, int y0, const __half* in) {
#pragma unroll
    for (int i = 0; i < 26; i++) {
        int unit = tid + i * 256;            // 6528 units of 16B
        if (unit < 6528) {
            int row = unit >> 3, c16 = unit & 7;
            int xh = row / 204;
            int rem = row - xh * 204;
            int yh = rem / 34;
            int zh = rem - yh * 34;
            int gx = x0 + xh - 1, gy = y0 + yh - 1, gz = zh - 1;
            bool ok = ((unsigned)gx < 32u) & ((unsigned)gy < 32u) & ((unsigned)gz < 32u);
            size_t off = 0;
            if (ok)
                off = ((((size_t)(b * 32 + gx)) * 32 + gy) * 32 + gz) * CIN
                    + h * 64 + c16 * 8;
            cp16(sb + row * PITCH + c16 * 16, in + off, ok ? 16u : 0u);
        }
    }
    asm volatile("cp.async.commit_group;" ::: "memory");
}

__device__ __forceinline__ void load_W(
    int c, int buf, u32 sb, int tid, const __half* wp) {
#pragma unroll
    for (int i = 0; i < 4; i++) {
        int unit = tid + i * 256;            // 1024 units of 16B
        int row = unit >> 3, c16 = unit & 7;
        size_t off = (size_t)c * (COUT * 64) + row * 64 + c16 * 8;
        cp16(sb + APLANE + buf * WTEN + row * PITCH + c16 * 16, wp + off, 16u);
    }
    asm volatile("cp.async.commit_group;" ::: "memory");
}

template <int CIN>
__global__ void __launch_bounds__(256, 1)
conv_mma_kernel(const float* __restrict__ bias,
                const float* __restrict__ gamma,
                const float* __restrict__ beta) {
    extern __shared__ __align__(128) char smem[];
    constexpr int L = (CIN == 128) ? 54 : 27;
    const u32 sb = smem_u32(smem);
    const int tid = threadIdx.x, w = tid >> 5, lane = tid & 31;
    const int x0 = blockIdx.x * 2, y0 = blockIdx.y * 4, b = blockIdx.z;
    const int wM = w >> 1, wN = w & 1;

    const __half* in = (CIN == 64) ? g_g0 : g_h1;
    const __half* wp = (CIN == 64) ? g_w1 : g_w2;

    float acc[4][8][4];                      // [m-tile][n8][frag]
#pragma unroll
    for (int mt = 0; mt < 4; mt++)
#pragma unroll
        for (int nn = 0; nn < 8; nn++)
#pragma unroll
            for (int j = 0; j < 4; j++) acc[mt][nn][j] = 0.f;

    load_Aplane<CIN>(0, sb, tid, b, x0, y0, in);
    load_W(0, 0, sb, tid, wp);

    const u32 b_row = (lane & 7) + ((lane >> 3) & 1) * 8;
    const u32 b_lane_off = (wN * 64 + b_row) * PITCH + (lane >> 4) * 16;
    const int a_xl = wM >> 1, a_yb = (wM & 1) * 2;

#pragma unroll 1
    for (int c = 0; c < L; c++) {
        asm volatile("cp.async.wait_group 0;" ::: "memory");
        __syncthreads();
        if (CIN == 128 && c == 27) {
            // new ci-half: reload A plane (all warps past compute of c-1)
            load_Aplane<CIN>(1, sb, tid, b, x0, y0, in);
            asm volatile("cp.async.wait_group 0;" ::: "memory");
            __syncthreads();
        }
        if (c + 1 < L) load_W(c + 1, (c + 1) & 1, sb, tid, wp);

        const int tap = (CIN == 128) ? (c % 27) : c;
        const int dx = tap / 9, dy = (tap / 3) % 3, dz = tap % 3;
        u32 a_addr[4];
#pragma unroll
        for (int mt = 0; mt < 4; mt++) {
            int rpl = (a_xl + dx) * 204 + (a_yb + (mt >> 1) + dy) * 34
                    + (mt & 1) * 16 + (lane & 15) + dz;
            a_addr[mt] = sb + rpl * PITCH + (lane >> 4) * 16;
        }
        const u32 wbase = sb + APLANE + (c & 1) * WTEN + b_lane_off;

#pragma unroll
        for (int ks = 0; ks < 4; ks++) {
            u32 a[4][4];
#pragma unroll
            for (int mt = 0; mt < 4; mt++)
                ldsm4(a[mt][0], a[mt][1], a[mt][2], a[mt][3], a_addr[mt] + ks * 32);
#pragma unroll
            for (int nt = 0; nt < 4; nt++) {
                u32 w0, w1, w2, w3;
                ldsm4(w0, w1, w2, w3, wbase + nt * 16 * PITCH + ks * 32);
#pragma unroll
                for (int mt = 0; mt < 4; mt++) {
                    mma16816(acc[mt][2 * nt],     a[mt][0], a[mt][1], a[mt][2], a[mt][3], w0, w2);
                    mma16816(acc[mt][2 * nt + 1], a[mt][0], a[mt][1], a[mt][2], a[mt][3], w1, w3);
                }
            }
        }
    }

    // ---- epilogue: bias + per-voxel GN(16 ch) + SiLU, straight from fragments ----
    const int r0 = lane >> 2, cq = lane & 3;
#pragma unroll
    for (int mt = 0; mt < 4; mt++) {
#pragma unroll
        for (int h = 0; h < 2; h++) {
            int row_m = wM * 64 + mt * 16 + r0 + h * 8;
            int xl = row_m >> 7, yl = (row_m >> 5) & 3, z = row_m & 31;
            size_t vox = (((size_t)(b * 32 + x0 + xl)) * 32 + (y0 + yl)) * 32 + z;
#pragma unroll
            for (int k = 0; k < 4; k++) {
                int cA = wN * 64 + k * 16 + cq * 2;
                int cB = cA + 8;
                float v[4];
                v[0] = acc[mt][2 * k][2 * h + 0]     + bias[cA + 0];
                v[1] = acc[mt][2 * k][2 * h + 1]     + bias[cA + 1];
                v[2] = acc[mt][2 * k + 1][2 * h + 0] + bias[cB + 0];
                v[3] = acc[mt][2 * k + 1][2 * h + 1] + bias[cB + 1];
                float s = v[0] + v[1] + v[2] + v[3];
                float q = v[0] * v[0] + v[1] * v[1] + v[2] * v[2] + v[3] * v[3];
                s += __shfl_xor_sync(0xffffffffu, s, 1);
                s += __shfl_xor_sync(0xffffffffu, s, 2);
                q += __shfl_xor_sync(0xffffffffu, q, 1);
                q += __shfl_xor_sync(0xffffffffu, q, 2);
                float mu  = s * (1.0f / 16.0f);
                float var = q * (1.0f / 16.0f) - mu * mu;
                float rs  = rsqrtf(var + 1e-5f);
                float y2[4];
#pragma unroll
                for (int j = 0; j < 4; j++) {
                    int col = (j < 2) ? (cA + j) : (cB + (j - 2));
                    float y = (v[j] - mu) * rs * gamma[col] + beta[col];
                    y2[j] = y / (1.0f + expf(-y));
                }
                if (CIN == 64) {
                    __half2 hA; hA.x = __float2half_rn(y2[0]); hA.y = __float2half_rn(y2[1]);
                    __half2 hB; hB.x = __float2half_rn(y2[2]); hB.y = __float2half_rn(y2[3]);
                    *(__half2*)&g_h1[vox * COUT + cA] = hA;
                    *(__half2*)&g_h1[vox * COUT + cB] = hB;
                } else {
                    *(float2*)&g_h2[vox * COUT + cA] = make_float2(y2[0], y2[1]);
                    *(float2*)&g_h2[vox * COUT + cB] = make_float2(y2[2], y2[3]);
                }
            }
        }
    }
}

// ---------------- point branch GEMM + global group stats ------------------------
__global__ void __launch_bounds__(128)
mlp_gstats_kernel(const float* __restrict__ feats,
                  const float* __restrict__ w,
                  const float* __restrict__ bias) {
    __shared__ float s_w[CIN0 * 129];
    __shared__ float s_f[CIN0 * 32];
    const int tid = threadIdx.x;
    const int b   = blockIdx.x >> 9;
    const int n0  = (blockIdx.x & 511) * 32;

    for (int i = tid; i < COUT * CIN0; i += 128) {
        int c = i >> 6, ci = i & 63;
        s_w[ci * 129 + c] = w[i];
    }
    for (int i = tid; i < CIN0 * 32; i += 128) {
        int ci = i >> 5, p = i & 31;
        s_f[ci * 32 + p] = feats[((size_t)b * CIN0 + ci) * NN + n0 + p];
    }
    __syncthreads();

    const int c = tid;
    float bv = bias[c];
    float lsum = 0.f, lsq = 0.f;
    for (int p = 0; p < 32; p++) {
        float a = bv;
#pragma unroll 16
        for (int ci = 0; ci < CIN0; ci++)
            a += s_w[ci * 129 + c] * s_f[ci * 32 + p];
        g_pf[((size_t)b * NN + n0 + p) * COUT + c] = a;
        lsum += a; lsq += a * a;
    }
#pragma unroll
    for (int o = 8; o >= 1; o >>= 1) {
        lsum += __shfl_xor_sync(0xffffffffu, lsum, o, 16);
        lsq  += __shfl_xor_sync(0xffffffffu, lsq,  o, 16);
    }
    if ((tid & 15) == 0) {
        int g = c >> 4;
        atomicAdd(&g_stats[(b * 8 + g) * 2 + 0], lsum);
        atomicAdd(&g_stats[(b * 8 + g) * 2 + 1], lsq);
    }
}

__global__ void stats_finalize_kernel() {
    int t = threadIdx.x;
    if (t >= BB * 8) return;
    const float inv = 1.0f / (16.0f * (float)NN);
    float s = g_stats[t * 2 + 0], s2 = g_stats[t * 2 + 1];
    float mu = s * inv;
    float var = s2 * inv - mu * mu;
    g_stats[t * 2 + 0] = mu;
    g_stats[t * 2 + 1] = rsqrtf(var + 1e-5f);
}

// ---------------- devoxelize + point GN/SiLU + add ------------------------------
__global__ void __launch_bounds__(128)
devox_out_kernel(const float* __restrict__ coords,
                 const float* __restrict__ gamma,
                 const float* __restrict__ beta,
                 float* __restrict__ out) {
    __shared__ float s_o[COUT * 17];
    const int c  = threadIdx.x;
    const int p0 = blockIdx.x * 16;
    const int b  = p0 >> 14;
    const int n0 = p0 & (NN - 1);
    const int g  = c >> 4;
    const float gm = gamma[c], bt = beta[c];
    const float mu = g_stats[(b * 8 + g) * 2 + 0];
    const float rs = g_stats[(b * 8 + g) * 2 + 1];

    for (int p = 0; p < 16; p++) {
        int gp = p0 + p;
        float cx = coords[gp * 3 + 0] * (float)RR;
        float cy = coords[gp * 3 + 1] * (float)RR;
        float cz = coords[gp * 3 + 2] * (float)RR;
        float fxl = floorf(cx), fyl = floorf(cy), fzl = floorf(cz);
        int ix = min(max((int)fxl, 0), RR - 1);
        int iy = min(max((int)fyl, 0), RR - 1);
        int iz = min(max((int)fzl, 0), RR - 1);
        int hx = min(ix + 1, RR - 1), hy = min(iy + 1, RR - 1), hz = min(iz + 1, RR - 1);
        float fx = cx - fxl, fy = cy - fyl, fz = cz - fzl;

        float v = 0.f;
#pragma unroll
        for (int dx = 0; dx < 2; dx++) {
            float wx = dx ? fx : 1.f - fx;
            int X = dx ? hx : ix;
#pragma unroll
            for (int dy = 0; dy < 2; dy++) {
                float wy = dy ? fy : 1.f - fy;
                int Y = dy ? hy : iy;
#pragma unroll
                for (int dz = 0; dz < 2; dz++) {
                    float wz = dz ? fz : 1.f - fz;
                    int Z = dz ? hz : iz;
                    size_t base = (((size_t)(b * RR + X) * RR + Y) * RR + Z) * COUT + c;
                    v += (wx * wy * wz) * g_h2[base];
                }
            }
        }
        float pv = g_pf[((size_t)gp) * COUT + c];
        float y  = (pv - mu) * rs * gm + bt;
        y = y / (1.0f + expf(-y));
        s_o[c * 17 + p] = v + y;
    }
    __syncthreads();
    for (int i = threadIdx.x; i < COUT * 16; i += 128) {
        int c2 = i >> 4, p = i & 15;
        out[((size_t)b * COUT + c2) * NN + n0 + p] = s_o[c2 * 17 + p];
    }
}

// ---------------- launch ----------------------------------------------------------
extern "C" void kernel_launch(void* const* d_in, const int* in_sizes, int n_in,
                              void* d_out, int out_size) {
    const float* coords   = (const float*)d_in[0];
    const float* features = (const float*)d_in[1];
    const float* conv1_w  = (const float*)d_in[2];
    const float* conv1_b  = (const float*)d_in[3];
    const float* gn1_g    = (const float*)d_in[4];
    const float* gn1_b    = (const float*)d_in[5];
    const float* conv2_w  = (const float*)d_in[6];
    const float* conv2_b  = (const float*)d_in[7];
    const float* gn2_g    = (const float*)d_in[8];
    const float* gn2_b    = (const float*)d_in[9];
    const float* mlp_w    = (const float*)d_in[10];
    const float* mlp_b    = (const float*)d_in[11];
    const float* gnp_g    = (const float*)d_in[12];
    const float* gnp_b    = (const float*)d_in[13];
    float* out = (float*)d_out;

    static int attr_done = 0;
    if (!attr_done) {
        cudaFuncSetAttribute(conv_mma_kernel<CIN0>,
                             cudaFuncAttributeMaxDynamicSharedMemorySize, CVSMEM);
        cudaFuncSetAttribute(conv_mma_kernel<COUT>,
                             cudaFuncAttributeMaxDynamicSharedMemorySize, CVSMEM);
        attr_done = 1;
    }

    zero_scratch_kernel<<<2048, 256>>>();
    wprep1_kernel<<<(COUT * 64 * 27 + 255) / 256, 256>>>(conv1_w);
    wprep2_kernel<<<(COUT * 128 * 27 + 255) / 256, 256>>>(conv2_w);

    scatter_kernel<<<(BB * NN * CIN0 + 255) / 256, 256>>>(coords, features);
    vox_split_kernel<<<4096, 256>>>();

    dim3 cgrid(RR / 2, 8, BB);   // x-pair, y-tile, b
    conv_mma_kernel<CIN0><<<cgrid, 256, CVSMEM>>>(conv1_b, gn1_g, gn1_b);
    conv_mma_kernel<COUT><<<cgrid, 256, CVSMEM>>>(conv2_b, gn2_g, gn2_b);

    mlp_gstats_kernel<<<BB * (NN / 32), 128>>>(features, mlp_w, mlp_b);
    stats_finalize_kernel<<<1, 32>>>();

    devox_out_kernel<<<BB * NN / 16, 128>>>(coords, gnp_g, gnp_b, out);
}